// round 1
// baseline (speedup 1.0000x reference)
#include <cuda_runtime.h>
#include <math.h>

// ---------------------------------------------------------------------------
// Problem constants (from reference): B=2, S=4096, D=1024, H=4*D=4096
// M = B*S = 8192 rows through all row-wise ops.
// ---------------------------------------------------------------------------
#define BB   2
#define SS   4096
#define DD   1024
#define HH   4096
#define MM   (BB * SS)   // 8192

// ---------------------------------------------------------------------------
// Scratch (static device globals; no runtime allocation allowed)
// ---------------------------------------------------------------------------
__device__ float g_q   [MM * DD];            // 32 MB
__device__ float g_k   [MM * DD];            // 32 MB
__device__ float g_v   [MM * DD];            // 32 MB
__device__ float g_attn[(long long)BB * SS * SS]; // 128 MB
__device__ float g_ao  [MM * DD];            // 32 MB
__device__ float g_x1  [MM * DD];            // 32 MB
__device__ float g_h   [(long long)MM * HH]; // 128 MB
__device__ float g_ff  [MM * DD];            // 32 MB

// ---------------------------------------------------------------------------
// Block reduction helper (sum or max), 256 threads
// ---------------------------------------------------------------------------
__device__ __forceinline__ float block_reduce(float v, bool do_max) {
    __shared__ float sh[33];
    #pragma unroll
    for (int o = 16; o > 0; o >>= 1) {
        float t = __shfl_xor_sync(0xffffffffu, v, o);
        v = do_max ? fmaxf(v, t) : (v + t);
    }
    const int lane = threadIdx.x & 31;
    const int wid  = threadIdx.x >> 5;
    if (lane == 0) sh[wid] = v;
    __syncthreads();
    if (wid == 0) {
        int nw = blockDim.x >> 5;
        v = (lane < nw) ? sh[lane] : (do_max ? -INFINITY : 0.0f);
        #pragma unroll
        for (int o = 16; o > 0; o >>= 1) {
            float t = __shfl_xor_sync(0xffffffffu, v, o);
            v = do_max ? fmaxf(v, t) : (v + t);
        }
        if (lane == 0) sh[32] = v;
    }
    __syncthreads();
    float r = sh[32];
    __syncthreads();   // protect shared reuse across back-to-back calls
    return r;
}

// ---------------------------------------------------------------------------
// SGEMM: C = A @ B (NN) or C = A @ B^T (NT), optional bias + exact GELU.
// BM=BN=128, BK=16, 256 threads, 8x8 per-thread tile. All dims tile-exact.
// blockIdx.z = batch, with byte-free element strides sA/sB/sC.
// ---------------------------------------------------------------------------
template <bool TRANS_B, bool GELU>
__global__ void __launch_bounds__(256)
gemm_kernel(const float* __restrict__ A, const float* __restrict__ Bm,
            const float* __restrict__ bias, float* __restrict__ C,
            int M, int N, int K,
            long long sA, long long sB, long long sC)
{
    constexpr int BM = 128, BN = 128, BK = 16, TM = 8, TN = 8;
    __shared__ float As[BK][BM + 4];
    __shared__ float Bs[BK][BN + 4];

    A  += (long long)blockIdx.z * sA;
    Bm += (long long)blockIdx.z * sB;
    C  += (long long)blockIdx.z * sC;

    const int tid = threadIdx.x;
    const int m0  = blockIdx.y * BM;
    const int n0  = blockIdx.x * BN;
    const int tx  = tid & 15;      // 0..15 -> n
    const int ty  = tid >> 4;      // 0..15 -> m

    float acc[TM][TN];
    #pragma unroll
    for (int i = 0; i < TM; ++i)
        #pragma unroll
        for (int j = 0; j < TN; ++j)
            acc[i][j] = 0.0f;

    const int lrow = tid >> 2;          // 0..63
    const int lk4  = (tid & 3) * 4;     // 0,4,8,12

    for (int k0 = 0; k0 < K; k0 += BK) {
        // ---- load A tile (transposed into smem) ----
        #pragma unroll
        for (int p = 0; p < 2; ++p) {
            int m = lrow + p * 64;
            float4 va = *(const float4*)(A + (long long)(m0 + m) * K + k0 + lk4);
            As[lk4 + 0][m] = va.x;
            As[lk4 + 1][m] = va.y;
            As[lk4 + 2][m] = va.z;
            As[lk4 + 3][m] = va.w;
        }
        // ---- load B tile ----
        if (TRANS_B) {
            // Bm is [N,K] row-major; Bs[k][n] = Bm[n, k]
            #pragma unroll
            for (int p = 0; p < 2; ++p) {
                int n = lrow + p * 64;
                float4 vb = *(const float4*)(Bm + (long long)(n0 + n) * K + k0 + lk4);
                Bs[lk4 + 0][n] = vb.x;
                Bs[lk4 + 1][n] = vb.y;
                Bs[lk4 + 2][n] = vb.z;
                Bs[lk4 + 3][n] = vb.w;
            }
        } else {
            // Bm is [K,N] row-major
            const int bk = tid >> 5;          // 0..7
            const int bn = (tid & 31) * 4;    // 0..124
            #pragma unroll
            for (int p = 0; p < 2; ++p) {
                int k = bk + p * 8;
                float4 vb = *(const float4*)(Bm + (long long)(k0 + k) * N + n0 + bn);
                Bs[k][bn + 0] = vb.x;
                Bs[k][bn + 1] = vb.y;
                Bs[k][bn + 2] = vb.z;
                Bs[k][bn + 3] = vb.w;
            }
        }
        __syncthreads();

        // ---- compute ----
        #pragma unroll
        for (int kk = 0; kk < BK; ++kk) {
            float a[TM], b[TN];
            #pragma unroll
            for (int i = 0; i < TM; ++i) a[i] = As[kk][ty * TM + i];
            #pragma unroll
            for (int j = 0; j < TN; ++j) b[j] = Bs[kk][tx * TN + j];
            #pragma unroll
            for (int i = 0; i < TM; ++i)
                #pragma unroll
                for (int j = 0; j < TN; ++j)
                    acc[i][j] = fmaf(a[i], b[j], acc[i][j]);
        }
        __syncthreads();
    }

    // ---- epilogue: bias + optional exact GELU ----
    #pragma unroll
    for (int i = 0; i < TM; ++i) {
        long long rowoff = (long long)(m0 + ty * TM + i) * N + n0 + tx * TN;
        #pragma unroll
        for (int j = 0; j < TN; ++j) {
            float val = acc[i][j];
            if (bias) val += bias[n0 + tx * TN + j];
            if (GELU) val = 0.5f * val * (1.0f + erff(val * 0.70710678118654752f));
            C[rowoff + j] = val;
        }
    }
}

// ---------------------------------------------------------------------------
// Softmax over rows of length 4096 (one block/row, values cached in regs)
// attn[row, :] = softmax(attn[row, :] * scale)
// ---------------------------------------------------------------------------
__global__ void __launch_bounds__(256)
softmax_kernel(float* __restrict__ attn, float scale)
{
    constexpr int T = SS;          // 4096
    constexpr int NT = 256;
    constexpr int VPT = T / NT;    // 16
    float* row = attn + (long long)blockIdx.x * T;
    const int tid = threadIdx.x;

    float r[VPT];
    float mx = -INFINITY;
    #pragma unroll
    for (int i = 0; i < VPT; ++i) {
        r[i] = row[tid + i * NT] * scale;
        mx = fmaxf(mx, r[i]);
    }
    mx = block_reduce(mx, true);

    float s = 0.0f;
    #pragma unroll
    for (int i = 0; i < VPT; ++i) {
        r[i] = expf(r[i] - mx);
        s += r[i];
    }
    s = block_reduce(s, false);
    float inv = 1.0f / s;

    #pragma unroll
    for (int i = 0; i < VPT; ++i)
        row[tid + i * NT] = r[i] * inv;
}

// ---------------------------------------------------------------------------
// out[row,:] = LayerNorm(X[row,:] + R[row,:]) * gamma + beta   (D = 1024)
// ---------------------------------------------------------------------------
__global__ void __launch_bounds__(256)
add_ln_kernel(const float* __restrict__ X, const float* __restrict__ R,
              const float* __restrict__ gamma, const float* __restrict__ beta,
              float* __restrict__ O)
{
    constexpr int D = DD;          // 1024
    constexpr int NT = 256;
    constexpr int VPT = D / NT;    // 4
    const long long base = (long long)blockIdx.x * D;
    const int tid = threadIdx.x;

    float v[VPT];
    float s = 0.0f;
    #pragma unroll
    for (int i = 0; i < VPT; ++i) {
        int d = tid + i * NT;
        v[i] = X[base + d] + R[base + d];
        s += v[i];
    }
    float mean = block_reduce(s, false) * (1.0f / D);

    float var = 0.0f;
    #pragma unroll
    for (int i = 0; i < VPT; ++i) {
        float dlt = v[i] - mean;
        var += dlt * dlt;
    }
    var = block_reduce(var, false) * (1.0f / D);
    float inv = rsqrtf(var + 1e-5f);

    #pragma unroll
    for (int i = 0; i < VPT; ++i) {
        int d = tid + i * NT;
        O[base + d] = (v[i] - mean) * inv * gamma[d] + beta[d];
    }
}

// ---------------------------------------------------------------------------
// kernel_launch
// Inputs (metadata order): input_embedding, Wq, bq, Wk, bk, Wv, bv,
//                          W1, b1, W2, b2, gamma, beta
// ---------------------------------------------------------------------------
extern "C" void kernel_launch(void* const* d_in, const int* /*in_sizes*/, int /*n_in*/,
                              void* d_out, int /*out_size*/)
{
    const float* x     = (const float*)d_in[0];
    const float* Wq    = (const float*)d_in[1];
    const float* bq    = (const float*)d_in[2];
    const float* Wk    = (const float*)d_in[3];
    const float* bk    = (const float*)d_in[4];
    const float* Wv    = (const float*)d_in[5];
    const float* bv    = (const float*)d_in[6];
    const float* W1    = (const float*)d_in[7];
    const float* b1    = (const float*)d_in[8];
    const float* W2    = (const float*)d_in[9];
    const float* b2    = (const float*)d_in[10];
    const float* gamma = (const float*)d_in[11];
    const float* beta  = (const float*)d_in[12];
    float* out = (float*)d_out;

    float *q, *k, *v, *attn, *ao, *x1, *h, *ff;
    cudaGetSymbolAddress((void**)&q,    g_q);
    cudaGetSymbolAddress((void**)&k,    g_k);
    cudaGetSymbolAddress((void**)&v,    g_v);
    cudaGetSymbolAddress((void**)&attn, g_attn);
    cudaGetSymbolAddress((void**)&ao,   g_ao);
    cudaGetSymbolAddress((void**)&x1,   g_x1);
    cudaGetSymbolAddress((void**)&h,    g_h);
    cudaGetSymbolAddress((void**)&ff,   g_ff);

    dim3 blk(256);

    // --- Q, K, V projections: [8192,1024] = x @ W + b ---
    dim3 gqkv(DD / 128, MM / 128, 1);
    gemm_kernel<false, false><<<gqkv, blk>>>(x, Wq, bq, q, MM, DD, DD, 0, 0, 0);
    gemm_kernel<false, false><<<gqkv, blk>>>(x, Wk, bk, k, MM, DD, DD, 0, 0, 0);
    gemm_kernel<false, false><<<gqkv, blk>>>(x, Wv, bv, v, MM, DD, DD, 0, 0, 0);

    // --- scores[b] = k[b] @ q[b]^T   (reference quirk: attention(k,q,v)) ---
    dim3 gsc(SS / 128, SS / 128, BB);
    gemm_kernel<true, false><<<gsc, blk>>>(
        k, q, nullptr, attn, SS, SS, DD,
        (long long)SS * DD, (long long)SS * DD, (long long)SS * SS);

    // --- softmax over last dim, scaled by 1/sqrt(D) = 1/32 ---
    softmax_kernel<<<MM, blk>>>(attn, 0.03125f);

    // --- ao[b] = attn[b] @ v[b] ---
    dim3 gav(DD / 128, SS / 128, BB);
    gemm_kernel<false, false><<<gav, blk>>>(
        attn, v, nullptr, ao, SS, DD, SS,
        (long long)SS * SS, (long long)SS * DD, (long long)SS * DD);

    // --- x1 = LayerNorm(x + ao) ---
    add_ln_kernel<<<MM, blk>>>(x, ao, gamma, beta, x1);

    // --- h = gelu(x1 @ W1 + b1) ---
    dim3 gf1(HH / 128, MM / 128, 1);
    gemm_kernel<false, true><<<gf1, blk>>>(x1, W1, b1, h, MM, HH, DD, 0, 0, 0);

    // --- ff = h @ W2 + b2 ---
    dim3 gf2(DD / 128, MM / 128, 1);
    gemm_kernel<false, false><<<gf2, blk>>>(h, W2, b2, ff, MM, DD, HH, 0, 0, 0);

    // --- out = LayerNorm(x1 + ff) ---
    add_ln_kernel<<<MM, blk>>>(x1, ff, gamma, beta, out);
}

// round 2
// speedup vs baseline: 2.6631x; 2.6631x over previous
#include <cuda_runtime.h>
#include <math.h>
#include <stdint.h>

// ---------------------------------------------------------------------------
// B=2, S=4096, D=1024, H=4096, M=B*S=8192
// ---------------------------------------------------------------------------
#define BB   2
#define SS   4096
#define DD   1024
#define HH   4096
#define MM   (BB * SS)

// ---------------------------------------------------------------------------
// Scratch (static device globals; no runtime allocation allowed)
// ---------------------------------------------------------------------------
__device__ float g_q   [MM * DD];
__device__ float g_k   [MM * DD];
__device__ float g_v   [MM * DD];
__device__ float g_attn[(long long)BB * SS * SS];
__device__ float g_ao  [MM * DD];
__device__ float g_x1  [MM * DD];
__device__ float g_h   [(long long)MM * HH];
__device__ float g_ff  [MM * DD];

// ---------------------------------------------------------------------------
// Helpers
// ---------------------------------------------------------------------------
__device__ __forceinline__ uint32_t f2tf32(float x) {
    uint32_t r;
    asm volatile("cvt.rna.tf32.f32 %0, %1;" : "=r"(r) : "f"(x));
    return r;
}

__device__ __forceinline__ void mma_tf32(float* c, const uint32_t* a, const uint32_t* b) {
    asm volatile(
        "mma.sync.aligned.m16n8k8.row.col.f32.tf32.tf32.f32 "
        "{%0,%1,%2,%3}, {%4,%5,%6,%7}, {%8,%9}, {%0,%1,%2,%3};\n"
        : "+f"(c[0]), "+f"(c[1]), "+f"(c[2]), "+f"(c[3])
        : "r"(a[0]), "r"(a[1]), "r"(a[2]), "r"(a[3]),
          "r"(b[0]), "r"(b[1]));
}

__device__ __forceinline__ void cp_async16(void* smem, const void* gmem) {
    uint32_t s = (uint32_t)__cvta_generic_to_shared(smem);
    asm volatile("cp.async.ca.shared.global [%0], [%1], 16;\n" :: "r"(s), "l"(gmem));
}
__device__ __forceinline__ void cp_commit() {
    asm volatile("cp.async.commit_group;\n");
}
__device__ __forceinline__ void cp_wait_all() {
    asm volatile("cp.async.wait_group 0;\n");
}

// ---------------------------------------------------------------------------
// tf32 tensor-core GEMM:
//   C = A @ B (NN, B is [K,N]) or C = A @ B^T (NT, B is [N,K])
//   optional bias + exact GELU epilogue. All dims multiples of tile sizes.
// CTA tile 128x128, BK=16, 256 threads (8 warps of 32x64), double-buffered
// cp.async smem pipeline.
// ---------------------------------------------------------------------------
template <bool TRANS_B, bool GELU>
__global__ void __launch_bounds__(256, 2)
gemm_tf32(const float* __restrict__ A, const float* __restrict__ Bm,
          const float* __restrict__ bias, float* __restrict__ C,
          int M, int N, int K,
          long long sA, long long sB, long long sC)
{
    constexpr int BM = 128, BN = 128, BK = 16;
    constexpr int LDA = BK + 4;                     // 20 floats (80B, 16B-mult)
    constexpr int LDB_NN = BN + 4;                  // 132 floats (528B)
    constexpr int BS_ELEMS = TRANS_B ? (BN * LDA) : (BK * LDB_NN);

    __shared__ float As[2][BM * LDA];
    __shared__ float Bs[2][BS_ELEMS];

    A  += (long long)blockIdx.z * sA;
    Bm += (long long)blockIdx.z * sB;
    C  += (long long)blockIdx.z * sC;

    const int tid  = threadIdx.x;
    const int lane = tid & 31;
    const int wid  = tid >> 5;
    const int m0   = blockIdx.y * BM;
    const int n0   = blockIdx.x * BN;
    const int wm   = (wid >> 1) * 32;   // warp M offset within CTA tile
    const int wn   = (wid & 1) * 64;    // warp N offset
    const int lr   = lane >> 2;         // 0..7
    const int lc   = lane & 3;          // 0..3

    float acc[2][8][4];
    #pragma unroll
    for (int i = 0; i < 2; ++i)
        #pragma unroll
        for (int j = 0; j < 8; ++j)
            #pragma unroll
            for (int t = 0; t < 4; ++t)
                acc[i][j][t] = 0.0f;

    // ---- async tile loaders ----
    auto load_tiles = [&](int buf, int k0) {
        // A tile: 128 rows x 16 cols = 512 float4, 2 per thread
        #pragma unroll
        for (int p = 0; p < 2; ++p) {
            int idx = tid + p * 256;
            int row = idx >> 2;
            int c4  = (idx & 3) << 2;
            cp_async16(&As[buf][row * LDA + c4],
                       A + (long long)(m0 + row) * K + k0 + c4);
        }
        if (TRANS_B) {
            // B [N,K]: 128 rows x 16 cols, store Bs[n][k]
            #pragma unroll
            for (int p = 0; p < 2; ++p) {
                int idx = tid + p * 256;
                int row = idx >> 2;
                int c4  = (idx & 3) << 2;
                cp_async16(&Bs[buf][row * LDA + c4],
                           Bm + (long long)(n0 + row) * K + k0 + c4);
            }
        } else {
            // B [K,N]: 16 rows x 128 cols, store Bs[k][n]
            #pragma unroll
            for (int p = 0; p < 2; ++p) {
                int idx = tid + p * 256;
                int row = idx >> 5;
                int c4  = (idx & 31) << 2;
                cp_async16(&Bs[buf][row * LDB_NN + c4],
                           Bm + (long long)(k0 + row) * N + n0 + c4);
            }
        }
        cp_commit();
    };

    const int NIT = K / BK;
    int buf = 0;
    load_tiles(0, 0);

    for (int it = 0; it < NIT; ++it) {
        cp_wait_all();
        __syncthreads();
        if (it + 1 < NIT) load_tiles(buf ^ 1, (it + 1) * BK);

        // ---- compute on buf: 2 k-steps of 8 ----
        #pragma unroll
        for (int ks = 0; ks < 2; ++ks) {
            const int kk = ks * 8;

            uint32_t af[2][4];
            #pragma unroll
            for (int mi = 0; mi < 2; ++mi) {
                const float* Ab = &As[buf][(wm + mi * 16) * LDA + kk];
                af[mi][0] = f2tf32(Ab[(lr    ) * LDA + lc    ]);
                af[mi][1] = f2tf32(Ab[(lr + 8) * LDA + lc    ]);
                af[mi][2] = f2tf32(Ab[(lr    ) * LDA + lc + 4]);
                af[mi][3] = f2tf32(Ab[(lr + 8) * LDA + lc + 4]);
            }

            uint32_t bf[8][2];
            #pragma unroll
            for (int nj = 0; nj < 8; ++nj) {
                if (TRANS_B) {
                    const float* Bb = &Bs[buf][(wn + nj * 8 + lr) * LDA + kk];
                    bf[nj][0] = f2tf32(Bb[lc    ]);
                    bf[nj][1] = f2tf32(Bb[lc + 4]);
                } else {
                    const float* Bb = &Bs[buf][(kk + lc) * LDB_NN + wn + nj * 8 + lr];
                    bf[nj][0] = f2tf32(Bb[0]);
                    bf[nj][1] = f2tf32(Bb[4 * LDB_NN]);
                }
            }

            #pragma unroll
            for (int mi = 0; mi < 2; ++mi)
                #pragma unroll
                for (int nj = 0; nj < 8; ++nj)
                    mma_tf32(acc[mi][nj], af[mi], bf[nj]);
        }
        __syncthreads();
        buf ^= 1;
    }

    // ---- epilogue: bias + optional exact GELU, float2 stores ----
    #pragma unroll
    for (int mi = 0; mi < 2; ++mi) {
        #pragma unroll
        for (int nj = 0; nj < 8; ++nj) {
            const int col = n0 + wn + nj * 8 + lc * 2;
            float b0 = 0.0f, b1 = 0.0f;
            if (bias) { b0 = bias[col]; b1 = bias[col + 1]; }
            #pragma unroll
            for (int half = 0; half < 2; ++half) {
                const int row = m0 + wm + mi * 16 + lr + half * 8;
                float v0 = acc[mi][nj][half * 2 + 0] + b0;
                float v1 = acc[mi][nj][half * 2 + 1] + b1;
                if (GELU) {
                    v0 = 0.5f * v0 * (1.0f + erff(v0 * 0.70710678118654752f));
                    v1 = 0.5f * v1 * (1.0f + erff(v1 * 0.70710678118654752f));
                }
                *(float2*)(C + (long long)row * N + col) = make_float2(v0, v1);
            }
        }
    }
}

// ---------------------------------------------------------------------------
// Block reduction helper (sum or max), 256 threads
// ---------------------------------------------------------------------------
__device__ __forceinline__ float block_reduce(float v, bool do_max) {
    __shared__ float sh[33];
    #pragma unroll
    for (int o = 16; o > 0; o >>= 1) {
        float t = __shfl_xor_sync(0xffffffffu, v, o);
        v = do_max ? fmaxf(v, t) : (v + t);
    }
    const int lane = threadIdx.x & 31;
    const int wid  = threadIdx.x >> 5;
    if (lane == 0) sh[wid] = v;
    __syncthreads();
    if (wid == 0) {
        int nw = blockDim.x >> 5;
        v = (lane < nw) ? sh[lane] : (do_max ? -INFINITY : 0.0f);
        #pragma unroll
        for (int o = 16; o > 0; o >>= 1) {
            float t = __shfl_xor_sync(0xffffffffu, v, o);
            v = do_max ? fmaxf(v, t) : (v + t);
        }
        if (lane == 0) sh[32] = v;
    }
    __syncthreads();
    float r = sh[32];
    __syncthreads();
    return r;
}

// ---------------------------------------------------------------------------
// Softmax over rows of length 4096 (one block/row, values in regs)
// ---------------------------------------------------------------------------
__global__ void __launch_bounds__(256)
softmax_kernel(float* __restrict__ attn, float scale)
{
    constexpr int T = SS, NT = 256, VPT = T / NT;
    float* row = attn + (long long)blockIdx.x * T;
    const int tid = threadIdx.x;

    float r[VPT];
    float mx = -INFINITY;
    #pragma unroll
    for (int i = 0; i < VPT; ++i) {
        r[i] = row[tid + i * NT] * scale;
        mx = fmaxf(mx, r[i]);
    }
    mx = block_reduce(mx, true);

    float s = 0.0f;
    #pragma unroll
    for (int i = 0; i < VPT; ++i) {
        r[i] = expf(r[i] - mx);
        s += r[i];
    }
    s = block_reduce(s, false);
    float inv = 1.0f / s;

    #pragma unroll
    for (int i = 0; i < VPT; ++i)
        row[tid + i * NT] = r[i] * inv;
}

// ---------------------------------------------------------------------------
// out = LayerNorm(X + R) * gamma + beta   (D = 1024)
// ---------------------------------------------------------------------------
__global__ void __launch_bounds__(256)
add_ln_kernel(const float* __restrict__ X, const float* __restrict__ R,
              const float* __restrict__ gamma, const float* __restrict__ beta,
              float* __restrict__ O)
{
    constexpr int D = DD, NT = 256, VPT = D / NT;
    const long long base = (long long)blockIdx.x * D;
    const int tid = threadIdx.x;

    float v[VPT];
    float s = 0.0f;
    #pragma unroll
    for (int i = 0; i < VPT; ++i) {
        int d = tid + i * NT;
        v[i] = X[base + d] + R[base + d];
        s += v[i];
    }
    float mean = block_reduce(s, false) * (1.0f / D);

    float var = 0.0f;
    #pragma unroll
    for (int i = 0; i < VPT; ++i) {
        float dlt = v[i] - mean;
        var += dlt * dlt;
    }
    var = block_reduce(var, false) * (1.0f / D);
    float inv = rsqrtf(var + 1e-5f);

    #pragma unroll
    for (int i = 0; i < VPT; ++i) {
        int d = tid + i * NT;
        O[base + d] = (v[i] - mean) * inv * gamma[d] + beta[d];
    }
}

// ---------------------------------------------------------------------------
// kernel_launch
// Inputs: input_embedding, Wq, bq, Wk, bk, Wv, bv, W1, b1, W2, b2, gamma, beta
// ---------------------------------------------------------------------------
extern "C" void kernel_launch(void* const* d_in, const int* /*in_sizes*/, int /*n_in*/,
                              void* d_out, int /*out_size*/)
{
    const float* x     = (const float*)d_in[0];
    const float* Wq    = (const float*)d_in[1];
    const float* bq    = (const float*)d_in[2];
    const float* Wk    = (const float*)d_in[3];
    const float* bk    = (const float*)d_in[4];
    const float* Wv    = (const float*)d_in[5];
    const float* bv    = (const float*)d_in[6];
    const float* W1    = (const float*)d_in[7];
    const float* b1    = (const float*)d_in[8];
    const float* W2    = (const float*)d_in[9];
    const float* b2    = (const float*)d_in[10];
    const float* gamma = (const float*)d_in[11];
    const float* beta  = (const float*)d_in[12];
    float* out = (float*)d_out;

    float *q, *k, *v, *attn, *ao, *x1, *h, *ff;
    cudaGetSymbolAddress((void**)&q,    g_q);
    cudaGetSymbolAddress((void**)&k,    g_k);
    cudaGetSymbolAddress((void**)&v,    g_v);
    cudaGetSymbolAddress((void**)&attn, g_attn);
    cudaGetSymbolAddress((void**)&ao,   g_ao);
    cudaGetSymbolAddress((void**)&x1,   g_x1);
    cudaGetSymbolAddress((void**)&h,    g_h);
    cudaGetSymbolAddress((void**)&ff,   g_ff);

    dim3 blk(256);

    // --- Q, K, V projections ---
    dim3 gqkv(DD / 128, MM / 128, 1);
    gemm_tf32<false, false><<<gqkv, blk>>>(x, Wq, bq, q, MM, DD, DD, 0, 0, 0);
    gemm_tf32<false, false><<<gqkv, blk>>>(x, Wk, bk, k, MM, DD, DD, 0, 0, 0);
    gemm_tf32<false, false><<<gqkv, blk>>>(x, Wv, bv, v, MM, DD, DD, 0, 0, 0);

    // --- scores[b] = k[b] @ q[b]^T (reference quirk: attention(k,q,v)) ---
    dim3 gsc(SS / 128, SS / 128, BB);
    gemm_tf32<true, false><<<gsc, blk>>>(
        k, q, nullptr, attn, SS, SS, DD,
        (long long)SS * DD, (long long)SS * DD, (long long)SS * SS);

    // --- softmax (scale = 1/sqrt(1024) = 1/32) ---
    softmax_kernel<<<MM, blk>>>(attn, 0.03125f);

    // --- ao[b] = attn[b] @ v[b] ---
    dim3 gav(DD / 128, SS / 128, BB);
    gemm_tf32<false, false><<<gav, blk>>>(
        attn, v, nullptr, ao, SS, DD, SS,
        (long long)SS * SS, (long long)SS * DD, (long long)SS * DD);

    // --- x1 = LayerNorm(x + ao) ---
    add_ln_kernel<<<MM, blk>>>(x, ao, gamma, beta, x1);

    // --- h = gelu(x1 @ W1 + b1) ---
    dim3 gf1(HH / 128, MM / 128, 1);
    gemm_tf32<false, true><<<gf1, blk>>>(x1, W1, b1, h, MM, HH, DD, 0, 0, 0);

    // --- ff = h @ W2 + b2 ---
    dim3 gf2(DD / 128, MM / 128, 1);
    gemm_tf32<false, false><<<gf2, blk>>>(h, W2, b2, ff, MM, DD, HH, 0, 0, 0);

    // --- out = LayerNorm(x1 + ff) ---
    add_ln_kernel<<<MM, blk>>>(x1, ff, gamma, beta, out);
}

// round 4
// speedup vs baseline: 2.9609x; 1.1118x over previous
#include <cuda_runtime.h>
#include <math.h>
#include <stdint.h>

// ---------------------------------------------------------------------------
// B=2, S=4096, D=1024, H=4096, M=B*S=8192
// ---------------------------------------------------------------------------
#define BB   2
#define SS   4096
#define DD   1024
#define HH   4096
#define MM   (BB * SS)

// ---------------------------------------------------------------------------
// Scratch (static device globals; no runtime allocation allowed)
// ---------------------------------------------------------------------------
__device__ float g_q   [MM * DD];
__device__ float g_k   [MM * DD];
__device__ float g_v   [MM * DD];
__device__ float g_attn[(long long)BB * SS * SS];
__device__ float g_ao  [MM * DD];
__device__ float g_x1  [MM * DD];
__device__ float g_h   [(long long)MM * HH];
__device__ float g_ff  [MM * DD];
__device__ float g_xr  [MM * DD];          // tf32-rounded input
__device__ float g_wqr [DD * DD];          // tf32-rounded weights
__device__ float g_wkr [DD * DD];
__device__ float g_wvr [DD * DD];
__device__ float g_w1r [(long long)DD * HH];
__device__ float g_w2r [(long long)HH * DD];

// ---------------------------------------------------------------------------
// Helpers
// ---------------------------------------------------------------------------
__device__ __forceinline__ float tf32_rna(float x) {
    uint32_t r;
    asm volatile("cvt.rna.tf32.f32 %0, %1;" : "=r"(r) : "f"(x));
    return __uint_as_float(r);
}

__device__ __forceinline__ void mma_tf32(float* c, const uint32_t* a, const uint32_t* b) {
    asm volatile(
        "mma.sync.aligned.m16n8k8.row.col.f32.tf32.tf32.f32 "
        "{%0,%1,%2,%3}, {%4,%5,%6,%7}, {%8,%9}, {%0,%1,%2,%3};\n"
        : "+f"(c[0]), "+f"(c[1]), "+f"(c[2]), "+f"(c[3])
        : "r"(a[0]), "r"(a[1]), "r"(a[2]), "r"(a[3]),
          "r"(b[0]), "r"(b[1]));
}

__device__ __forceinline__ void cp_async16(void* smem, const void* gmem) {
    uint32_t s = (uint32_t)__cvta_generic_to_shared(smem);
    asm volatile("cp.async.ca.shared.global [%0], [%1], 16;\n" :: "r"(s), "l"(gmem));
}
__device__ __forceinline__ void cp_commit() {
    asm volatile("cp.async.commit_group;\n");
}
__device__ __forceinline__ void cp_wait_all() {
    asm volatile("cp.async.wait_group 0;\n");
}

// ---------------------------------------------------------------------------
// tf32 tensor-core GEMM, operands PRE-ROUNDED to tf32 (raw bits fed to HMMA).
//   C = A @ B (NN, B is [K,N]) or C = A @ B^T (NT, B is [N,K])
//   optional bias, exact GELU, tf32 rounding of output.
// CTA tile 128x256, BK=16, 256 threads = 8 warps of 64x64.
// All dims multiples of tile sizes.
// ---------------------------------------------------------------------------
template <bool TRANS_B, bool GELU, bool ROUND>
__global__ void __launch_bounds__(256, 1)
gemm_tf32(const float* __restrict__ A, const float* __restrict__ Bm,
          const float* __restrict__ bias, float* __restrict__ C,
          int M, int N, int K,
          long long sA, long long sB, long long sC)
{
    constexpr int BM = 128, BN = 256, BK = 16;
    constexpr int LDA    = BK + 4;   // 20: conflict-free for frag loads
    constexpr int LDB_NT = BK + 4;   // 20
    constexpr int LDB_NN = BN + 8;   // 264
    constexpr int A_STAGE = BM * LDA;                                 // 2560
    constexpr int B_STAGE = TRANS_B ? (BN * LDB_NT) : (BK * LDB_NN);  // 5120 / 4224

    extern __shared__ uint32_t smem_u[];
    uint32_t* As = smem_u;                 // [2][A_STAGE]
    uint32_t* Bs = smem_u + 2 * A_STAGE;   // [2][B_STAGE]

    A  += (long long)blockIdx.z * sA;
    Bm += (long long)blockIdx.z * sB;
    C  += (long long)blockIdx.z * sC;

    const int tid  = threadIdx.x;
    const int lane = tid & 31;
    const int wid  = tid >> 5;
    const int m0   = blockIdx.y * BM;
    const int n0   = blockIdx.x * BN;
    const int wm   = (wid & 1) * 64;     // warp M offset
    const int wn   = (wid >> 1) * 64;    // warp N offset
    const int lr   = lane >> 2;          // 0..7
    const int lc   = lane & 3;           // 0..3

    float acc[4][8][4];
    #pragma unroll
    for (int i = 0; i < 4; ++i)
        #pragma unroll
        for (int j = 0; j < 8; ++j)
            #pragma unroll
            for (int t = 0; t < 4; ++t)
                acc[i][j][t] = 0.0f;

    auto load_tiles = [&](int buf, int k0) {
        // A tile: 128 rows x 16 floats = 512 16B-chunks, 2 per thread
        #pragma unroll
        for (int p = 0; p < 2; ++p) {
            int idx = tid + p * 256;
            int row = idx >> 2;
            int c4  = (idx & 3) << 2;
            cp_async16(&As[buf * A_STAGE + row * LDA + c4],
                       A + (long long)(m0 + row) * K + k0 + c4);
        }
        if (TRANS_B) {
            // B [N,K]: 256 rows x 16 floats, Bs[n][k]
            #pragma unroll
            for (int p = 0; p < 4; ++p) {
                int idx = tid + p * 256;
                int row = idx >> 2;
                int c4  = (idx & 3) << 2;
                cp_async16(&Bs[buf * B_STAGE + row * LDB_NT + c4],
                           Bm + (long long)(n0 + row) * K + k0 + c4);
            }
        } else {
            // B [K,N]: 16 rows x 256 floats, Bs[k][n]
            #pragma unroll
            for (int p = 0; p < 4; ++p) {
                int idx = tid + p * 256;
                int row = idx >> 6;
                int c4  = (idx & 63) << 2;
                cp_async16(&Bs[buf * B_STAGE + row * LDB_NN + c4],
                           Bm + (long long)(k0 + row) * N + n0 + c4);
            }
        }
        cp_commit();
    };

    const int NIT = K / BK;
    int buf = 0;
    load_tiles(0, 0);

    for (int it = 0; it < NIT; ++it) {
        cp_wait_all();
        __syncthreads();
        if (it + 1 < NIT) load_tiles(buf ^ 1, (it + 1) * BK);

        #pragma unroll
        for (int ks = 0; ks < 2; ++ks) {
            const int kk = ks * 8;

            uint32_t a[4][4];
            #pragma unroll
            for (int mi = 0; mi < 4; ++mi) {
                const uint32_t* Ab = &As[buf * A_STAGE + (wm + mi * 16 + lr) * LDA + kk + lc];
                a[mi][0] = Ab[0];
                a[mi][1] = Ab[8 * LDA];
                a[mi][2] = Ab[4];
                a[mi][3] = Ab[8 * LDA + 4];
            }

            uint32_t b[8][2];
            #pragma unroll
            for (int nj = 0; nj < 8; ++nj) {
                if (TRANS_B) {
                    const uint32_t* Bb = &Bs[buf * B_STAGE + (wn + nj * 8 + lr) * LDB_NT + kk + lc];
                    b[nj][0] = Bb[0];
                    b[nj][1] = Bb[4];
                } else {
                    const uint32_t* Bb = &Bs[buf * B_STAGE + (kk + lc) * LDB_NN + wn + nj * 8 + lr];
                    b[nj][0] = Bb[0];
                    b[nj][1] = Bb[4 * LDB_NN];
                }
            }

            #pragma unroll
            for (int mi = 0; mi < 4; ++mi)
                #pragma unroll
                for (int nj = 0; nj < 8; ++nj)
                    mma_tf32(acc[mi][nj], a[mi], b[nj]);
        }
        __syncthreads();
        buf ^= 1;
    }

    // ---- epilogue: bias, exact GELU, optional tf32 rounding ----
    #pragma unroll
    for (int mi = 0; mi < 4; ++mi) {
        #pragma unroll
        for (int nj = 0; nj < 8; ++nj) {
            const int col = n0 + wn + nj * 8 + lc * 2;
            float b0 = 0.0f, b1 = 0.0f;
            if (bias) { b0 = bias[col]; b1 = bias[col + 1]; }
            #pragma unroll
            for (int half = 0; half < 2; ++half) {
                const int row = m0 + wm + mi * 16 + lr + half * 8;
                float v0 = acc[mi][nj][half * 2 + 0] + b0;
                float v1 = acc[mi][nj][half * 2 + 1] + b1;
                if (GELU) {
                    v0 = 0.5f * v0 * (1.0f + erff(v0 * 0.70710678118654752f));
                    v1 = 0.5f * v1 * (1.0f + erff(v1 * 0.70710678118654752f));
                }
                if (ROUND) { v0 = tf32_rna(v0); v1 = tf32_rna(v1); }
                *(float2*)(C + (long long)row * N + col) = make_float2(v0, v1);
            }
        }
    }
}

// ---------------------------------------------------------------------------
// Elementwise tf32 rounding: out[i] = rna_tf32(in[i]), n multiple of 4
// ---------------------------------------------------------------------------
__global__ void __launch_bounds__(256)
round_tf32_kernel(const float4* __restrict__ in, float4* __restrict__ out, long long n4)
{
    long long i = (long long)blockIdx.x * blockDim.x + threadIdx.x;
    long long stride = (long long)gridDim.x * blockDim.x;
    for (; i < n4; i += stride) {
        float4 v = in[i];
        v.x = tf32_rna(v.x); v.y = tf32_rna(v.y);
        v.z = tf32_rna(v.z); v.w = tf32_rna(v.w);
        out[i] = v;
    }
}

// ---------------------------------------------------------------------------
// Block reduction helper (sum or max), 256 threads
// ---------------------------------------------------------------------------
__device__ __forceinline__ float block_reduce(float v, bool do_max) {
    __shared__ float sh[33];
    #pragma unroll
    for (int o = 16; o > 0; o >>= 1) {
        float t = __shfl_xor_sync(0xffffffffu, v, o);
        v = do_max ? fmaxf(v, t) : (v + t);
    }
    const int lane = threadIdx.x & 31;
    const int wid  = threadIdx.x >> 5;
    if (lane == 0) sh[wid] = v;
    __syncthreads();
    if (wid == 0) {
        int nw = blockDim.x >> 5;
        v = (lane < nw) ? sh[lane] : (do_max ? -INFINITY : 0.0f);
        #pragma unroll
        for (int o = 16; o > 0; o >>= 1) {
            float t = __shfl_xor_sync(0xffffffffu, v, o);
            v = do_max ? fmaxf(v, t) : (v + t);
        }
        if (lane == 0) sh[32] = v;
    }
    __syncthreads();
    float r = sh[32];
    __syncthreads();
    return r;
}

// ---------------------------------------------------------------------------
// Softmax over rows of length 4096; output rounded to tf32 (feeds next GEMM)
// ---------------------------------------------------------------------------
__global__ void __launch_bounds__(256)
softmax_kernel(float* __restrict__ attn, float scale)
{
    constexpr int T = SS, NT = 256, VPT = T / NT;
    float* row = attn + (long long)blockIdx.x * T;
    const int tid = threadIdx.x;

    float r[VPT];
    float mx = -INFINITY;
    #pragma unroll
    for (int i = 0; i < VPT; ++i) {
        r[i] = row[tid + i * NT] * scale;
        mx = fmaxf(mx, r[i]);
    }
    mx = block_reduce(mx, true);

    float s = 0.0f;
    #pragma unroll
    for (int i = 0; i < VPT; ++i) {
        r[i] = expf(r[i] - mx);
        s += r[i];
    }
    s = block_reduce(s, false);
    float inv = 1.0f / s;

    #pragma unroll
    for (int i = 0; i < VPT; ++i)
        row[tid + i * NT] = tf32_rna(r[i] * inv);
}

// ---------------------------------------------------------------------------
// out = LayerNorm(X + R) * gamma + beta, optional tf32 rounding of output
// ---------------------------------------------------------------------------
__global__ void __launch_bounds__(256)
add_ln_kernel(const float* __restrict__ X, const float* __restrict__ R,
              const float* __restrict__ gamma, const float* __restrict__ beta,
              float* __restrict__ O, int do_round)
{
    constexpr int D = DD, NT = 256, VPT = D / NT;
    const long long base = (long long)blockIdx.x * D;
    const int tid = threadIdx.x;

    float v[VPT];
    float s = 0.0f;
    #pragma unroll
    for (int i = 0; i < VPT; ++i) {
        int d = tid + i * NT;
        v[i] = X[base + d] + R[base + d];
        s += v[i];
    }
    float mean = block_reduce(s, false) * (1.0f / D);

    float var = 0.0f;
    #pragma unroll
    for (int i = 0; i < VPT; ++i) {
        float dlt = v[i] - mean;
        var += dlt * dlt;
    }
    var = block_reduce(var, false) * (1.0f / D);
    float inv = rsqrtf(var + 1e-5f);

    #pragma unroll
    for (int i = 0; i < VPT; ++i) {
        int d = tid + i * NT;
        float o = (v[i] - mean) * inv * gamma[d] + beta[d];
        O[base + d] = do_round ? tf32_rna(o) : o;
    }
}

// ---------------------------------------------------------------------------
// kernel_launch
// Inputs: input_embedding, Wq, bq, Wk, bk, Wv, bv, W1, b1, W2, b2, gamma, beta
// ---------------------------------------------------------------------------
extern "C" void kernel_launch(void* const* d_in, const int* /*in_sizes*/, int /*n_in*/,
                              void* d_out, int /*out_size*/)
{
    const float* x     = (const float*)d_in[0];
    const float* Wq    = (const float*)d_in[1];
    const float* bq    = (const float*)d_in[2];
    const float* Wk    = (const float*)d_in[3];
    const float* bk    = (const float*)d_in[4];
    const float* Wv    = (const float*)d_in[5];
    const float* bv    = (const float*)d_in[6];
    const float* W1    = (const float*)d_in[7];
    const float* b1    = (const float*)d_in[8];
    const float* W2    = (const float*)d_in[9];
    const float* b2    = (const float*)d_in[10];
    const float* gamma = (const float*)d_in[11];
    const float* beta  = (const float*)d_in[12];
    float* out = (float*)d_out;

    float *q, *k, *v, *attn, *ao, *x1, *h, *ff, *xr, *wqr, *wkr, *wvr, *w1r, *w2r;
    cudaGetSymbolAddress((void**)&q,    g_q);
    cudaGetSymbolAddress((void**)&k,    g_k);
    cudaGetSymbolAddress((void**)&v,    g_v);
    cudaGetSymbolAddress((void**)&attn, g_attn);
    cudaGetSymbolAddress((void**)&ao,   g_ao);
    cudaGetSymbolAddress((void**)&x1,   g_x1);
    cudaGetSymbolAddress((void**)&h,    g_h);
    cudaGetSymbolAddress((void**)&ff,   g_ff);
    cudaGetSymbolAddress((void**)&xr,   g_xr);
    cudaGetSymbolAddress((void**)&wqr,  g_wqr);
    cudaGetSymbolAddress((void**)&wkr,  g_wkr);
    cudaGetSymbolAddress((void**)&wvr,  g_wvr);
    cudaGetSymbolAddress((void**)&w1r,  g_w1r);
    cudaGetSymbolAddress((void**)&w2r,  g_w2r);

    // dynamic smem: max over variants = (2*2560 + 2*5120) * 4 = 61440 B
    const int SMEM = 61440;
    cudaFuncSetAttribute((const void*)gemm_tf32<false, false, true>,
                         cudaFuncAttributeMaxDynamicSharedMemorySize, SMEM);
    cudaFuncSetAttribute((const void*)gemm_tf32<true,  false, false>,
                         cudaFuncAttributeMaxDynamicSharedMemorySize, SMEM);
    cudaFuncSetAttribute((const void*)gemm_tf32<false, false, false>,
                         cudaFuncAttributeMaxDynamicSharedMemorySize, SMEM);
    cudaFuncSetAttribute((const void*)gemm_tf32<false, true,  true>,
                         cudaFuncAttributeMaxDynamicSharedMemorySize, SMEM);

    dim3 blk(256);

    // --- pre-round GEMM operands to tf32 ---
    round_tf32_kernel<<<1184, blk>>>((const float4*)x,  (float4*)xr,  (long long)MM * DD / 4);
    round_tf32_kernel<<<592,  blk>>>((const float4*)Wq, (float4*)wqr, (long long)DD * DD / 4);
    round_tf32_kernel<<<592,  blk>>>((const float4*)Wk, (float4*)wkr, (long long)DD * DD / 4);
    round_tf32_kernel<<<592,  blk>>>((const float4*)Wv, (float4*)wvr, (long long)DD * DD / 4);
    round_tf32_kernel<<<1184, blk>>>((const float4*)W1, (float4*)w1r, (long long)DD * HH / 4);
    round_tf32_kernel<<<1184, blk>>>((const float4*)W2, (float4*)w2r, (long long)HH * DD / 4);

    // --- Q, K, V projections: [8192,1024] (outputs rounded) ---
    dim3 gqkv(DD / 256, MM / 128, 1);
    gemm_tf32<false, false, true><<<gqkv, blk, SMEM>>>(xr, wqr, bq, q, MM, DD, DD, 0, 0, 0);
    gemm_tf32<false, false, true><<<gqkv, blk, SMEM>>>(xr, wkr, bk, k, MM, DD, DD, 0, 0, 0);
    gemm_tf32<false, false, true><<<gqkv, blk, SMEM>>>(xr, wvr, bv, v, MM, DD, DD, 0, 0, 0);

    // --- scores[b] = k[b] @ q[b]^T (reference quirk: attention(k,q,v)) ---
    dim3 gsc(SS / 256, SS / 128, BB);
    gemm_tf32<true, false, false><<<gsc, blk, SMEM>>>(
        k, q, nullptr, attn, SS, SS, DD,
        (long long)SS * DD, (long long)SS * DD, (long long)SS * SS);

    // --- softmax (scale = 1/32), output rounded ---
    softmax_kernel<<<MM, blk>>>(attn, 0.03125f);

    // --- ao[b] = attn[b] @ v[b] ---
    dim3 gav(DD / 256, SS / 128, BB);
    gemm_tf32<false, false, false><<<gav, blk, SMEM>>>(
        attn, v, nullptr, ao, SS, DD, SS,
        (long long)SS * SS, (long long)SS * DD, (long long)SS * DD);

    // --- x1 = LayerNorm(x + ao), rounded (feeds FFN1) ---
    add_ln_kernel<<<MM, blk>>>(x, ao, gamma, beta, x1, 1);

    // --- h = gelu(x1 @ W1 + b1), rounded ---
    dim3 gf1(HH / 256, MM / 128, 1);
    gemm_tf32<false, true, true><<<gf1, blk, SMEM>>>(x1, w1r, b1, h, MM, HH, DD, 0, 0, 0);

    // --- ff = h @ W2 + b2 ---
    dim3 gf2(DD / 256, MM / 128, 1);
    gemm_tf32<false, false, false><<<gf2, blk, SMEM>>>(h, w2r, b2, ff, MM, DD, HH, 0, 0, 0);

    // --- out = LayerNorm(x1 + ff), full precision ---
    add_ln_kernel<<<MM, blk>>>(x1, ff, gamma, beta, out, 0);
}

// round 5
// speedup vs baseline: 5.0775x; 1.7148x over previous
#include <cuda_runtime.h>
#include <cuda_fp16.h>
#include <math.h>
#include <stdint.h>

// ---------------------------------------------------------------------------
// B=2, S=4096, D=1024, H=4096, M=B*S=8192
// ---------------------------------------------------------------------------
#define BB   2
#define SS   4096
#define DD   1024
#define HH   4096
#define MM   (BB * SS)

// ---------------------------------------------------------------------------
// Scratch (static device globals; no runtime allocation allowed)
// ---------------------------------------------------------------------------
__device__ __half g_xh  [MM * DD];                  // input, half
__device__ __half g_wqT [DD * DD];                  // weights, half, [N][K]
__device__ __half g_wkT [DD * DD];
__device__ __half g_wvT [DD * DD];
__device__ __half g_w1T [(long long)HH * DD];
__device__ __half g_w2T [(long long)DD * HH];
__device__ __half g_qh  [MM * DD];
__device__ __half g_kh  [MM * DD];
__device__ __half g_vh  [MM * DD];
__device__ __half g_vT  [(long long)BB * DD * SS];  // v transposed per batch
__device__ float  g_sc  [(long long)BB * SS * SS];  // fp32 logits (128 MB)
__device__ __half g_at  [(long long)BB * SS * SS];  // half attn weights (64 MB)
__device__ float  g_ao  [MM * DD];
__device__ float  g_x1f [MM * DD];
__device__ __half g_x1h [MM * DD];
__device__ __half g_hh  [(long long)MM * HH];       // gelu output, half (64 MB)
__device__ float  g_ff  [MM * DD];

// ---------------------------------------------------------------------------
// Helpers
// ---------------------------------------------------------------------------
__device__ __forceinline__ void mma_f16(float* c, const uint32_t* a, const uint32_t* b) {
    asm volatile(
        "mma.sync.aligned.m16n8k16.row.col.f32.f16.f16.f32 "
        "{%0,%1,%2,%3}, {%4,%5,%6,%7}, {%8,%9}, {%0,%1,%2,%3};\n"
        : "+f"(c[0]), "+f"(c[1]), "+f"(c[2]), "+f"(c[3])
        : "r"(a[0]), "r"(a[1]), "r"(a[2]), "r"(a[3]),
          "r"(b[0]), "r"(b[1]));
}
__device__ __forceinline__ void cp_async16(void* smem, const void* gmem) {
    uint32_t s = (uint32_t)__cvta_generic_to_shared(smem);
    asm volatile("cp.async.ca.shared.global [%0], [%1], 16;\n" :: "r"(s), "l"(gmem));
}
__device__ __forceinline__ void cp_commit() {
    asm volatile("cp.async.commit_group;\n");
}
__device__ __forceinline__ void cp_wait_all() {
    asm volatile("cp.async.wait_group 0;\n");
}

// ---------------------------------------------------------------------------
// fp16 tensor-core GEMM (NT only): C[M,N] = A[M,K] @ Bt[N,K]^T (+bias,+GELU).
// A, Bt are __half row-major; C is float or __half per OUT_HALF.
// CTA tile 128x256, BK=32, 256 threads = 8 warps of 64x64 (m16n8k16 frags).
// All dims multiples of tile sizes; K multiple of 32.
// ---------------------------------------------------------------------------
template <bool GELU, bool OUT_HALF>
__global__ void __launch_bounds__(256, 1)
gemm_h(const __half* __restrict__ A, const __half* __restrict__ Bt,
       const float* __restrict__ bias, void* __restrict__ Cv,
       int M, int N, int K,
       long long sA, long long sB, long long sC)
{
    constexpr int BM = 128, BN = 256, BK = 32;
    constexpr int LDH2   = 20;            // half2 words per row (16 data + 4 pad)
    constexpr int A_STAGE = BM * LDH2;    // 2560 words
    constexpr int B_STAGE = BN * LDH2;    // 5120 words

    extern __shared__ uint32_t smem_u[];
    uint32_t* As = smem_u;                // [2][A_STAGE]
    uint32_t* Bs = smem_u + 2 * A_STAGE;  // [2][B_STAGE]

    A  += (long long)blockIdx.z * sA;
    Bt += (long long)blockIdx.z * sB;

    const int tid  = threadIdx.x;
    const int lane = tid & 31;
    const int wid  = tid >> 5;
    const int m0   = blockIdx.y * BM;
    const int n0   = blockIdx.x * BN;
    const int wm   = (wid & 1) * 64;      // warp M offset
    const int wn   = (wid >> 1) * 64;     // warp N offset
    const int lr   = lane >> 2;           // 0..7
    const int lc   = lane & 3;            // 0..3

    float acc[4][8][4];
    #pragma unroll
    for (int i = 0; i < 4; ++i)
        #pragma unroll
        for (int j = 0; j < 8; ++j)
            #pragma unroll
            for (int t = 0; t < 4; ++t)
                acc[i][j][t] = 0.0f;

    auto load_tiles = [&](int buf, int k0) {
        // A tile: 128 rows x 32 halves = 4 chunks of 16B per row; 2 per thread
        #pragma unroll
        for (int p = 0; p < 2; ++p) {
            int idx = tid + p * 256;
            int row = idx >> 2;
            int ch  = idx & 3;
            cp_async16(&As[buf * A_STAGE + row * LDH2 + ch * 4],
                       A + (long long)(m0 + row) * K + k0 + ch * 8);
        }
        // B tile: 256 rows x 32 halves; 4 per thread
        #pragma unroll
        for (int p = 0; p < 4; ++p) {
            int idx = tid + p * 256;
            int row = idx >> 2;
            int ch  = idx & 3;
            cp_async16(&Bs[buf * B_STAGE + row * LDH2 + ch * 4],
                       Bt + (long long)(n0 + row) * K + k0 + ch * 8);
        }
        cp_commit();
    };

    const int NIT = K / BK;
    int buf = 0;
    load_tiles(0, 0);

    for (int it = 0; it < NIT; ++it) {
        cp_wait_all();
        __syncthreads();
        if (it + 1 < NIT) load_tiles(buf ^ 1, (it + 1) * BK);

        #pragma unroll
        for (int ks = 0; ks < 2; ++ks) {            // two k16 steps per BK=32
            const int kk = ks * 8;                  // in half2 units

            uint32_t a[4][4];
            #pragma unroll
            for (int mi = 0; mi < 4; ++mi) {
                const uint32_t* Ab =
                    &As[buf * A_STAGE + (wm + mi * 16 + lr) * LDH2 + kk + lc];
                a[mi][0] = Ab[0];
                a[mi][1] = Ab[8 * LDH2];
                a[mi][2] = Ab[4];
                a[mi][3] = Ab[8 * LDH2 + 4];
            }
            uint32_t b[8][2];
            #pragma unroll
            for (int nj = 0; nj < 8; ++nj) {
                const uint32_t* Bb =
                    &Bs[buf * B_STAGE + (wn + nj * 8 + lr) * LDH2 + kk + lc];
                b[nj][0] = Bb[0];
                b[nj][1] = Bb[4];
            }
            #pragma unroll
            for (int mi = 0; mi < 4; ++mi)
                #pragma unroll
                for (int nj = 0; nj < 8; ++nj)
                    mma_f16(acc[mi][nj], a[mi], b[nj]);
        }
        __syncthreads();
        buf ^= 1;
    }

    // ---- epilogue ----
    float*  Cf = (float*) Cv + (long long)blockIdx.z * sC;
    __half* Ch = (__half*)Cv + (long long)blockIdx.z * sC;
    #pragma unroll
    for (int mi = 0; mi < 4; ++mi) {
        #pragma unroll
        for (int nj = 0; nj < 8; ++nj) {
            const int col = n0 + wn + nj * 8 + lc * 2;
            float b0 = 0.0f, b1 = 0.0f;
            if (bias) { b0 = bias[col]; b1 = bias[col + 1]; }
            #pragma unroll
            for (int half_ = 0; half_ < 2; ++half_) {
                const int row = m0 + wm + mi * 16 + lr + half_ * 8;
                float v0 = acc[mi][nj][half_ * 2 + 0] + b0;
                float v1 = acc[mi][nj][half_ * 2 + 1] + b1;
                if (GELU) {
                    v0 = 0.5f * v0 * (1.0f + erff(v0 * 0.70710678118654752f));
                    v1 = 0.5f * v1 * (1.0f + erff(v1 * 0.70710678118654752f));
                }
                if (OUT_HALF) {
                    *(__half2*)(Ch + (long long)row * N + col) = __floats2half2_rn(v0, v1);
                } else {
                    *(float2*)(Cf + (long long)row * N + col) = make_float2(v0, v1);
                }
            }
        }
    }
}

// ---------------------------------------------------------------------------
// Elementwise fp32 -> half
// ---------------------------------------------------------------------------
__global__ void __launch_bounds__(256)
f2h_kernel(const float4* __restrict__ in, __half2* __restrict__ out, long long n4)
{
    long long i = (long long)blockIdx.x * blockDim.x + threadIdx.x;
    long long stride = (long long)gridDim.x * blockDim.x;
    for (; i < n4; i += stride) {
        float4 v = in[i];
        out[2 * i + 0] = __floats2half2_rn(v.x, v.y);
        out[2 * i + 1] = __floats2half2_rn(v.z, v.w);
    }
}

// ---------------------------------------------------------------------------
// Transpose fp32 [R][C] -> half [C][R]   (R, C multiples of 32)
// ---------------------------------------------------------------------------
__global__ void __launch_bounds__(256)
transpose_f2h(const float* __restrict__ in, __half* __restrict__ out, int R, int C)
{
    __shared__ float t[32][33];
    int x = blockIdx.x * 32 + threadIdx.x;
    int y = blockIdx.y * 32 + threadIdx.y;
    #pragma unroll
    for (int i = 0; i < 32; i += 8)
        t[threadIdx.y + i][threadIdx.x] = in[(long long)(y + i) * C + x];
    __syncthreads();
    x = blockIdx.y * 32 + threadIdx.x;
    y = blockIdx.x * 32 + threadIdx.y;
    #pragma unroll
    for (int i = 0; i < 32; i += 8)
        out[(long long)(y + i) * R + x] = __float2half_rn(t[threadIdx.x][threadIdx.y + i]);
}

// ---------------------------------------------------------------------------
// Transpose half [R][C] -> half [C][R], batched via z (lossless via float tile)
// ---------------------------------------------------------------------------
__global__ void __launch_bounds__(256)
transpose_h(const __half* __restrict__ in, __half* __restrict__ out,
            int R, int C, long long sIn, long long sOut)
{
    __shared__ float t[32][33];
    in  += (long long)blockIdx.z * sIn;
    out += (long long)blockIdx.z * sOut;
    int x = blockIdx.x * 32 + threadIdx.x;
    int y = blockIdx.y * 32 + threadIdx.y;
    #pragma unroll
    for (int i = 0; i < 32; i += 8)
        t[threadIdx.y + i][threadIdx.x] = __half2float(in[(long long)(y + i) * C + x]);
    __syncthreads();
    x = blockIdx.y * 32 + threadIdx.x;
    y = blockIdx.x * 32 + threadIdx.y;
    #pragma unroll
    for (int i = 0; i < 32; i += 8)
        out[(long long)(y + i) * R + x] = __float2half_rn(t[threadIdx.x][threadIdx.y + i]);
}

// ---------------------------------------------------------------------------
// Block reduction helper (sum or max), 256 threads
// ---------------------------------------------------------------------------
__device__ __forceinline__ float block_reduce(float v, bool do_max) {
    __shared__ float sh[33];
    #pragma unroll
    for (int o = 16; o > 0; o >>= 1) {
        float t = __shfl_xor_sync(0xffffffffu, v, o);
        v = do_max ? fmaxf(v, t) : (v + t);
    }
    const int lane = threadIdx.x & 31;
    const int wid  = threadIdx.x >> 5;
    if (lane == 0) sh[wid] = v;
    __syncthreads();
    if (wid == 0) {
        int nw = blockDim.x >> 5;
        v = (lane < nw) ? sh[lane] : (do_max ? -INFINITY : 0.0f);
        #pragma unroll
        for (int o = 16; o > 0; o >>= 1) {
            float t = __shfl_xor_sync(0xffffffffu, v, o);
            v = do_max ? fmaxf(v, t) : (v + t);
        }
        if (lane == 0) sh[32] = v;
    }
    __syncthreads();
    float r = sh[32];
    __syncthreads();
    return r;
}

// ---------------------------------------------------------------------------
// Softmax: fp32 logits in, half probabilities out (rows of 4096)
// ---------------------------------------------------------------------------
__global__ void __launch_bounds__(256)
softmax_kernel(const float* __restrict__ sc, __half* __restrict__ at, float scale)
{
    constexpr int T = SS, NT = 256, VPT = T / NT;
    const float*  row = sc + (long long)blockIdx.x * T;
    __half*       orow = at + (long long)blockIdx.x * T;
    const int tid = threadIdx.x;

    float r[VPT];
    float mx = -INFINITY;
    #pragma unroll
    for (int i = 0; i < VPT; ++i) {
        r[i] = row[tid + i * NT] * scale;
        mx = fmaxf(mx, r[i]);
    }
    mx = block_reduce(mx, true);

    float s = 0.0f;
    #pragma unroll
    for (int i = 0; i < VPT; ++i) {
        r[i] = expf(r[i] - mx);
        s += r[i];
    }
    s = block_reduce(s, false);
    float inv = 1.0f / s;

    #pragma unroll
    for (int i = 0; i < VPT; ++i)
        orow[tid + i * NT] = __float2half_rn(r[i] * inv);
}

// ---------------------------------------------------------------------------
// out = LayerNorm(X + R) * gamma + beta; fp32 out, optional half copy
// ---------------------------------------------------------------------------
__global__ void __launch_bounds__(256)
add_ln_kernel(const float* __restrict__ X, const float* __restrict__ R,
              const float* __restrict__ gamma, const float* __restrict__ beta,
              float* __restrict__ O, __half* __restrict__ Oh)
{
    constexpr int D = DD, NT = 256, VPT = D / NT;
    const long long base = (long long)blockIdx.x * D;
    const int tid = threadIdx.x;

    float v[VPT];
    float s = 0.0f;
    #pragma unroll
    for (int i = 0; i < VPT; ++i) {
        int d = tid + i * NT;
        v[i] = X[base + d] + R[base + d];
        s += v[i];
    }
    float mean = block_reduce(s, false) * (1.0f / D);

    float var = 0.0f;
    #pragma unroll
    for (int i = 0; i < VPT; ++i) {
        float dlt = v[i] - mean;
        var += dlt * dlt;
    }
    var = block_reduce(var, false) * (1.0f / D);
    float inv = rsqrtf(var + 1e-5f);

    #pragma unroll
    for (int i = 0; i < VPT; ++i) {
        int d = tid + i * NT;
        float o = (v[i] - mean) * inv * gamma[d] + beta[d];
        O[base + d] = o;
        if (Oh) Oh[base + d] = __float2half_rn(o);
    }
}

// ---------------------------------------------------------------------------
// kernel_launch
// Inputs: input_embedding, Wq, bq, Wk, bk, Wv, bv, W1, b1, W2, b2, gamma, beta
// ---------------------------------------------------------------------------
extern "C" void kernel_launch(void* const* d_in, const int* /*in_sizes*/, int /*n_in*/,
                              void* d_out, int /*out_size*/)
{
    const float* x     = (const float*)d_in[0];
    const float* Wq    = (const float*)d_in[1];
    const float* bq    = (const float*)d_in[2];
    const float* Wk    = (const float*)d_in[3];
    const float* bk    = (const float*)d_in[4];
    const float* Wv    = (const float*)d_in[5];
    const float* bv    = (const float*)d_in[6];
    const float* W1    = (const float*)d_in[7];
    const float* b1    = (const float*)d_in[8];
    const float* W2    = (const float*)d_in[9];
    const float* b2    = (const float*)d_in[10];
    const float* gamma = (const float*)d_in[11];
    const float* beta  = (const float*)d_in[12];
    float* out = (float*)d_out;

    __half *xh, *wqT, *wkT, *wvT, *w1T, *w2T, *qh, *kh, *vh, *vT, *at, *x1h, *hh;
    float *sc, *ao, *x1f, *ff;
    cudaGetSymbolAddress((void**)&xh,  g_xh);
    cudaGetSymbolAddress((void**)&wqT, g_wqT);
    cudaGetSymbolAddress((void**)&wkT, g_wkT);
    cudaGetSymbolAddress((void**)&wvT, g_wvT);
    cudaGetSymbolAddress((void**)&w1T, g_w1T);
    cudaGetSymbolAddress((void**)&w2T, g_w2T);
    cudaGetSymbolAddress((void**)&qh,  g_qh);
    cudaGetSymbolAddress((void**)&kh,  g_kh);
    cudaGetSymbolAddress((void**)&vh,  g_vh);
    cudaGetSymbolAddress((void**)&vT,  g_vT);
    cudaGetSymbolAddress((void**)&sc,  g_sc);
    cudaGetSymbolAddress((void**)&at,  g_at);
    cudaGetSymbolAddress((void**)&ao,  g_ao);
    cudaGetSymbolAddress((void**)&x1f, g_x1f);
    cudaGetSymbolAddress((void**)&x1h, g_x1h);
    cudaGetSymbolAddress((void**)&hh,  g_hh);
    cudaGetSymbolAddress((void**)&ff,  g_ff);

    const int SMEM = (2 * 2560 + 2 * 5120) * 4;   // 61440 B
    cudaFuncSetAttribute((const void*)gemm_h<false, true>,
                         cudaFuncAttributeMaxDynamicSharedMemorySize, SMEM);
    cudaFuncSetAttribute((const void*)gemm_h<false, false>,
                         cudaFuncAttributeMaxDynamicSharedMemorySize, SMEM);
    cudaFuncSetAttribute((const void*)gemm_h<true, true>,
                         cudaFuncAttributeMaxDynamicSharedMemorySize, SMEM);

    dim3 blk(256);
    dim3 tblk(32, 8);

    // --- prep: half input + half transposed weights ---
    f2h_kernel<<<1184, blk>>>((const float4*)x, (__half2*)xh, (long long)MM * DD / 4);
    transpose_f2h<<<dim3(DD/32, DD/32), tblk>>>(Wq, wqT, DD, DD);
    transpose_f2h<<<dim3(DD/32, DD/32), tblk>>>(Wk, wkT, DD, DD);
    transpose_f2h<<<dim3(DD/32, DD/32), tblk>>>(Wv, wvT, DD, DD);
    transpose_f2h<<<dim3(HH/32, DD/32), tblk>>>(W1, w1T, DD, HH);
    transpose_f2h<<<dim3(DD/32, HH/32), tblk>>>(W2, w2T, HH, DD);

    // --- Q, K, V projections (half out) ---
    dim3 gqkv(DD / 256, MM / 128, 1);
    gemm_h<false, true><<<gqkv, blk, SMEM>>>(xh, wqT, bq, qh, MM, DD, DD, 0, 0, 0);
    gemm_h<false, true><<<gqkv, blk, SMEM>>>(xh, wkT, bk, kh, MM, DD, DD, 0, 0, 0);
    gemm_h<false, true><<<gqkv, blk, SMEM>>>(xh, wvT, bv, vh, MM, DD, DD, 0, 0, 0);

    // --- logits[b] = k[b] @ q[b]^T (reference quirk: attention(k,q,v)); fp32 out ---
    dim3 gsc(SS / 256, SS / 128, BB);
    gemm_h<false, false><<<gsc, blk, SMEM>>>(
        kh, qh, nullptr, sc, SS, SS, DD,
        (long long)SS * DD, (long long)SS * DD, (long long)SS * SS);

    // --- softmax (scale = 1/32), half out ---
    softmax_kernel<<<MM, blk>>>(sc, at, 0.03125f);

    // --- vT[b] = v[b]^T (half) ---
    transpose_h<<<dim3(DD/32, SS/32, BB), tblk>>>(
        vh, vT, SS, DD, (long long)SS * DD, (long long)DD * SS);

    // --- ao[b] = attn[b] @ vT[b]^T (fp32 out) ---
    dim3 gav(DD / 256, SS / 128, BB);
    gemm_h<false, false><<<gav, blk, SMEM>>>(
        at, vT, nullptr, ao, SS, DD, SS,
        (long long)SS * SS, (long long)DD * SS, (long long)SS * DD);

    // --- x1 = LayerNorm(x + ao); fp32 + half copies ---
    add_ln_kernel<<<MM, blk>>>(x, ao, gamma, beta, x1f, x1h);

    // --- h = gelu(x1 @ W1 + b1), half out ---
    dim3 gf1(HH / 256, MM / 128, 1);
    gemm_h<true, true><<<gf1, blk, SMEM>>>(x1h, w1T, b1, hh, MM, HH, DD, 0, 0, 0);

    // --- ff = h @ W2 + b2, fp32 out ---
    dim3 gf2(DD / 256, MM / 128, 1);
    gemm_h<false, false><<<gf2, blk, SMEM>>>(hh, w2T, b2, ff, MM, DD, HH, 0, 0, 0);

    // --- out = LayerNorm(x1 + ff), fp32 ---
    add_ln_kernel<<<MM, blk>>>(x1f, ff, gamma, beta, out, nullptr);
}

// round 6
// speedup vs baseline: 5.7527x; 1.1330x over previous
#include <cuda_runtime.h>
#include <cuda_fp16.h>
#include <math.h>
#include <stdint.h>

// ---------------------------------------------------------------------------
// B=2, S=4096, D=1024, H=4096, M=B*S=8192
// ---------------------------------------------------------------------------
#define BB   2
#define SS   4096
#define DD   1024
#define HH   4096
#define MM   (BB * SS)

// ---------------------------------------------------------------------------
// Scratch (static device globals; no runtime allocation allowed)
// ---------------------------------------------------------------------------
__device__ __half g_xh   [MM * DD];                    // input, half
__device__ __half g_wqkvT[3 * DD * DD];                // [3072][1024] concat Wq/Wk/Wv^T
__device__ float  g_bqkv [3 * DD];                     // concat biases
__device__ __half g_w1T  [(long long)HH * DD];
__device__ __half g_w2T  [(long long)DD * HH];
__device__ __half g_qkv  [(long long)MM * 3 * DD];     // fused qkv out [8192][3072]
__device__ __half g_vT   [(long long)BB * DD * SS];    // v transposed per batch
__device__ __half g_at   [(long long)BB * SS * SS];    // half logits -> probs (64 MB)
__device__ float  g_ao   [MM * DD];
__device__ float  g_x1f  [MM * DD];
__device__ __half g_x1h  [MM * DD];
__device__ __half g_hh   [(long long)MM * HH];         // gelu output, half
__device__ float  g_ff   [MM * DD];

// ---------------------------------------------------------------------------
// PTX helpers
// ---------------------------------------------------------------------------
__device__ __forceinline__ void mma_f16(float* c, const uint32_t* a, const uint32_t* b) {
    asm volatile(
        "mma.sync.aligned.m16n8k16.row.col.f32.f16.f16.f32 "
        "{%0,%1,%2,%3}, {%4,%5,%6,%7}, {%8,%9}, {%0,%1,%2,%3};\n"
        : "+f"(c[0]), "+f"(c[1]), "+f"(c[2]), "+f"(c[3])
        : "r"(a[0]), "r"(a[1]), "r"(a[2]), "r"(a[3]),
          "r"(b[0]), "r"(b[1]));
}
__device__ __forceinline__ void ldsm_x4(uint32_t* r, uint32_t saddr) {
    asm volatile(
        "ldmatrix.sync.aligned.m8n8.x4.shared.b16 {%0,%1,%2,%3}, [%4];"
        : "=r"(r[0]), "=r"(r[1]), "=r"(r[2]), "=r"(r[3]) : "r"(saddr));
}
__device__ __forceinline__ void cp_async16(uint32_t saddr, const void* gmem) {
    asm volatile("cp.async.cg.shared.global [%0], [%1], 16;\n" :: "r"(saddr), "l"(gmem));
}
__device__ __forceinline__ void cp_commit() {
    asm volatile("cp.async.commit_group;\n");
}
__device__ __forceinline__ void cp_wait1() {
    asm volatile("cp.async.wait_group 1;\n");
}

// ---------------------------------------------------------------------------
// fp16 tensor-core GEMM (NT): C[M,N] = A[M,K] @ Bt[N,K]^T (+bias, +GELU).
// A, Bt half row-major with element strides lda/ldb; C float or half (ldc=N).
// CTA tile 128x256, BK=32, 256 threads = 8 warps of 64x64.
// 3-stage cp.async pipeline + ldmatrix.x4 fragment loads.
// M,N multiples of tile; K multiple of 32 (K/32 >= 2).
// ---------------------------------------------------------------------------
template <bool GELU, bool OUT_HALF>
__global__ void __launch_bounds__(256, 1)
gemm_h(const __half* __restrict__ A, const __half* __restrict__ Bt,
       const float* __restrict__ bias, void* __restrict__ Cv,
       int M, int N, int K, int lda, int ldb,
       long long sA, long long sB, long long sC)
{
    constexpr int BM = 128, BN = 256, BK = 32;
    constexpr int LDH2 = 20;                    // u32 words per smem row (16+4 pad)
    constexpr int A_STAGE = BM * LDH2;          // 2560 words
    constexpr int B_STAGE = BN * LDH2;          // 5120 words
    constexpr int STAGE   = A_STAGE + B_STAGE;  // 7680 words

    extern __shared__ uint32_t smem_u[];
    const uint32_t sbase = (uint32_t)__cvta_generic_to_shared(smem_u);

    A  += (long long)blockIdx.z * sA;
    Bt += (long long)blockIdx.z * sB;

    const int tid  = threadIdx.x;
    const int lane = tid & 31;
    const int wid  = tid >> 5;
    const int m0   = blockIdx.y * BM;
    const int n0   = blockIdx.x * BN;
    const int wm   = (wid & 1) * 64;
    const int wn   = (wid >> 1) * 64;
    const int lr   = lane >> 2;
    const int lc   = lane & 3;

    float acc[4][8][4];
    #pragma unroll
    for (int i = 0; i < 4; ++i)
        #pragma unroll
        for (int j = 0; j < 8; ++j)
            #pragma unroll
            for (int t = 0; t < 4; ++t)
                acc[i][j][t] = 0.0f;

    // ldmatrix per-lane byte offsets within a stage
    uint32_t a_off[4], b_off[4];
    {
        int arow  = wm + (lane & 15);
        int acol2 = (lane >> 4) * 4;
        #pragma unroll
        for (int mi = 0; mi < 4; ++mi)
            a_off[mi] = (uint32_t)(((arow + mi * 16) * LDH2 + acol2) * 4);
        int brow  = wn + (lane & 7) + ((lane >> 4) & 1) * 8;
        int bcol2 = ((lane >> 3) & 1) * 4;
        #pragma unroll
        for (int p = 0; p < 4; ++p)
            b_off[p] = (uint32_t)((A_STAGE + (brow + p * 16) * LDH2 + bcol2) * 4);
    }

    auto load_tile = [&](int t) {
        const uint32_t stg = sbase + (uint32_t)((t % 3) * STAGE * 4);
        const int k0 = t * BK;
        // A: 128 rows x 4 chunks of 16B; 2 per thread
        #pragma unroll
        for (int p = 0; p < 2; ++p) {
            int idx = tid + p * 256;
            int row = idx >> 2, ch = idx & 3;
            cp_async16(stg + (uint32_t)((row * LDH2 + ch * 4) * 4),
                       A + (long long)(m0 + row) * lda + k0 + ch * 8);
        }
        // B: 256 rows x 4 chunks; 4 per thread
        #pragma unroll
        for (int p = 0; p < 4; ++p) {
            int idx = tid + p * 256;
            int row = idx >> 2, ch = idx & 3;
            cp_async16(stg + (uint32_t)((A_STAGE + row * LDH2 + ch * 4) * 4),
                       Bt + (long long)(n0 + row) * ldb + k0 + ch * 8);
        }
    };

    const int NIT = K / BK;
    load_tile(0); cp_commit();
    load_tile(1); cp_commit();

    for (int it = 0; it < NIT; ++it) {
        cp_wait1();                 // stage `it` resident
        __syncthreads();            // all threads done reading buffer (it+2)%3
        if (it + 2 < NIT) load_tile(it + 2);
        cp_commit();                // exactly one group per iteration

        const uint32_t stg = sbase + (uint32_t)((it % 3) * STAGE * 4);
        #pragma unroll
        for (int ks = 0; ks < 2; ++ks) {
            const uint32_t kb = (uint32_t)(ks * 8 * 4);   // half2 offset in bytes

            uint32_t a[4][4];
            #pragma unroll
            for (int mi = 0; mi < 4; ++mi)
                ldsm_x4(a[mi], stg + a_off[mi] + kb);

            uint32_t b[8][2];
            #pragma unroll
            for (int p = 0; p < 4; ++p) {
                uint32_t r[4];
                ldsm_x4(r, stg + b_off[p] + kb);
                b[2 * p + 0][0] = r[0];
                b[2 * p + 0][1] = r[1];
                b[2 * p + 1][0] = r[2];
                b[2 * p + 1][1] = r[3];
            }
            #pragma unroll
            for (int mi = 0; mi < 4; ++mi)
                #pragma unroll
                for (int nj = 0; nj < 8; ++nj)
                    mma_f16(acc[mi][nj], a[mi], b[nj]);
        }
    }

    // ---- epilogue ----
    float*  Cf = (float*) Cv + (long long)blockIdx.z * sC;
    __half* Ch = (__half*)Cv + (long long)blockIdx.z * sC;
    #pragma unroll
    for (int mi = 0; mi < 4; ++mi) {
        #pragma unroll
        for (int nj = 0; nj < 8; ++nj) {
            const int col = n0 + wn + nj * 8 + lc * 2;
            float b0 = 0.0f, b1 = 0.0f;
            if (bias) { b0 = bias[col]; b1 = bias[col + 1]; }
            #pragma unroll
            for (int hf = 0; hf < 2; ++hf) {
                const int row = m0 + wm + mi * 16 + lr + hf * 8;
                float v0 = acc[mi][nj][hf * 2 + 0] + b0;
                float v1 = acc[mi][nj][hf * 2 + 1] + b1;
                if (GELU) {
                    v0 = 0.5f * v0 * (1.0f + erff(v0 * 0.70710678118654752f));
                    v1 = 0.5f * v1 * (1.0f + erff(v1 * 0.70710678118654752f));
                }
                if (OUT_HALF) {
                    *(__half2*)(Ch + (long long)row * N + col) = __floats2half2_rn(v0, v1);
                } else {
                    *(float2*)(Cf + (long long)row * N + col) = make_float2(v0, v1);
                }
            }
        }
    }
}

// ---------------------------------------------------------------------------
// Elementwise fp32 -> half
// ---------------------------------------------------------------------------
__global__ void __launch_bounds__(256)
f2h_kernel(const float4* __restrict__ in, __half2* __restrict__ out, long long n4)
{
    long long i = (long long)blockIdx.x * blockDim.x + threadIdx.x;
    long long stride = (long long)gridDim.x * blockDim.x;
    for (; i < n4; i += stride) {
        float4 v = in[i];
        out[2 * i + 0] = __floats2half2_rn(v.x, v.y);
        out[2 * i + 1] = __floats2half2_rn(v.z, v.w);
    }
}

// ---------------------------------------------------------------------------
// Transpose fp32 [R][C] -> half [C][R]
// ---------------------------------------------------------------------------
__global__ void __launch_bounds__(256)
transpose_f2h(const float* __restrict__ in, __half* __restrict__ out, int R, int C)
{
    __shared__ float t[32][33];
    int x = blockIdx.x * 32 + threadIdx.x;
    int y = blockIdx.y * 32 + threadIdx.y;
    #pragma unroll
    for (int i = 0; i < 32; i += 8)
        t[threadIdx.y + i][threadIdx.x] = in[(long long)(y + i) * C + x];
    __syncthreads();
    x = blockIdx.y * 32 + threadIdx.x;
    y = blockIdx.x * 32 + threadIdx.y;
    #pragma unroll
    for (int i = 0; i < 32; i += 8)
        out[(long long)(y + i) * R + x] = __float2half_rn(t[threadIdx.x][threadIdx.y + i]);
}

// ---------------------------------------------------------------------------
// Transpose half [R][C-view] -> half [C][R], input row stride ldIn, batched
// ---------------------------------------------------------------------------
__global__ void __launch_bounds__(256)
transpose_h(const __half* __restrict__ in, __half* __restrict__ out,
            int R, int C, int ldIn, long long sIn, long long sOut)
{
    __shared__ __half t[32][40];
    in  += (long long)blockIdx.z * sIn;
    out += (long long)blockIdx.z * sOut;
    int x = blockIdx.x * 32 + threadIdx.x;
    int y = blockIdx.y * 32 + threadIdx.y;
    #pragma unroll
    for (int i = 0; i < 32; i += 8)
        t[threadIdx.y + i][threadIdx.x] = in[(long long)(y + i) * ldIn + x];
    __syncthreads();
    x = blockIdx.y * 32 + threadIdx.x;
    y = blockIdx.x * 32 + threadIdx.y;
    #pragma unroll
    for (int i = 0; i < 32; i += 8)
        out[(long long)(y + i) * R + x] = t[threadIdx.x][threadIdx.y + i];
}

// ---------------------------------------------------------------------------
// Block reduction helper (sum or max), 256 threads
// ---------------------------------------------------------------------------
__device__ __forceinline__ float block_reduce(float v, bool do_max) {
    __shared__ float sh[33];
    #pragma unroll
    for (int o = 16; o > 0; o >>= 1) {
        float t = __shfl_xor_sync(0xffffffffu, v, o);
        v = do_max ? fmaxf(v, t) : (v + t);
    }
    const int lane = threadIdx.x & 31;
    const int wid  = threadIdx.x >> 5;
    if (lane == 0) sh[wid] = v;
    __syncthreads();
    if (wid == 0) {
        int nw = blockDim.x >> 5;
        v = (lane < nw) ? sh[lane] : (do_max ? -INFINITY : 0.0f);
        #pragma unroll
        for (int o = 16; o > 0; o >>= 1) {
            float t = __shfl_xor_sync(0xffffffffu, v, o);
            v = do_max ? fmaxf(v, t) : (v + t);
        }
        if (lane == 0) sh[32] = v;
    }
    __syncthreads();
    float r = sh[32];
    __syncthreads();
    return r;
}

// ---------------------------------------------------------------------------
// Softmax in-place on half rows of 4096 (logits -> probs)
// ---------------------------------------------------------------------------
__global__ void __launch_bounds__(256)
softmax_h(__half* __restrict__ at, float scale)
{
    constexpr int T2 = SS / 2, NT = 256, VPT = T2 / NT;   // 8 half2 per thread
    __half2* row = (__half2*)(at + (long long)blockIdx.x * SS);
    const int tid = threadIdx.x;

    float2 r[VPT];
    float mx = -INFINITY;
    #pragma unroll
    for (int i = 0; i < VPT; ++i) {
        float2 f = __half22float2(row[tid + i * NT]);
        r[i].x = f.x * scale; r[i].y = f.y * scale;
        mx = fmaxf(mx, fmaxf(r[i].x, r[i].y));
    }
    mx = block_reduce(mx, true);

    float s = 0.0f;
    #pragma unroll
    for (int i = 0; i < VPT; ++i) {
        r[i].x = expf(r[i].x - mx);
        r[i].y = expf(r[i].y - mx);
        s += r[i].x + r[i].y;
    }
    s = block_reduce(s, false);
    float inv = 1.0f / s;

    #pragma unroll
    for (int i = 0; i < VPT; ++i)
        row[tid + i * NT] = __floats2half2_rn(r[i].x * inv, r[i].y * inv);
}

// ---------------------------------------------------------------------------
// out = LayerNorm(X + R) * gamma + beta; fp32 out, optional half copy.
// One block per row, float4 vectorized (D=1024, 256 threads).
// ---------------------------------------------------------------------------
__global__ void __launch_bounds__(256)
add_ln_kernel(const float* __restrict__ X, const float* __restrict__ R,
              const float* __restrict__ gamma, const float* __restrict__ beta,
              float* __restrict__ O, __half* __restrict__ Oh)
{
    constexpr int D = DD;
    const long long base = (long long)blockIdx.x * D;
    const int d = threadIdx.x * 4;

    float4 xv = *(const float4*)(X + base + d);
    float4 rv = *(const float4*)(R + base + d);
    float4 v  = make_float4(xv.x + rv.x, xv.y + rv.y, xv.z + rv.z, xv.w + rv.w);

    float mean = block_reduce(v.x + v.y + v.z + v.w, false) * (1.0f / D);

    float4 dv = make_float4(v.x - mean, v.y - mean, v.z - mean, v.w - mean);
    float var = block_reduce(dv.x * dv.x + dv.y * dv.y + dv.z * dv.z + dv.w * dv.w,
                             false) * (1.0f / D);
    float inv = rsqrtf(var + 1e-5f);

    float4 gv = *(const float4*)(gamma + d);
    float4 bv = *(const float4*)(beta + d);
    float4 o;
    o.x = dv.x * inv * gv.x + bv.x;
    o.y = dv.y * inv * gv.y + bv.y;
    o.z = dv.z * inv * gv.z + bv.z;
    o.w = dv.w * inv * gv.w + bv.w;
    *(float4*)(O + base + d) = o;
    if (Oh) {
        *(__half2*)(Oh + base + d)     = __floats2half2_rn(o.x, o.y);
        *(__half2*)(Oh + base + d + 2) = __floats2half2_rn(o.z, o.w);
    }
}

// ---------------------------------------------------------------------------
// kernel_launch
// Inputs: input_embedding, Wq, bq, Wk, bk, Wv, bv, W1, b1, W2, b2, gamma, beta
// ---------------------------------------------------------------------------
extern "C" void kernel_launch(void* const* d_in, const int* /*in_sizes*/, int /*n_in*/,
                              void* d_out, int /*out_size*/)
{
    const float* x     = (const float*)d_in[0];
    const float* Wq    = (const float*)d_in[1];
    const float* bq    = (const float*)d_in[2];
    const float* Wk    = (const float*)d_in[3];
    const float* bk    = (const float*)d_in[4];
    const float* Wv    = (const float*)d_in[5];
    const float* bv    = (const float*)d_in[6];
    const float* W1    = (const float*)d_in[7];
    const float* b1    = (const float*)d_in[8];
    const float* W2    = (const float*)d_in[9];
    const float* b2    = (const float*)d_in[10];
    const float* gamma = (const float*)d_in[11];
    const float* beta  = (const float*)d_in[12];
    float* out = (float*)d_out;

    __half *xh, *wqkvT, *w1T, *w2T, *qkv, *vT, *at, *x1h, *hh;
    float *bqkv, *ao, *x1f, *ff;
    cudaGetSymbolAddress((void**)&xh,    g_xh);
    cudaGetSymbolAddress((void**)&wqkvT, g_wqkvT);
    cudaGetSymbolAddress((void**)&bqkv,  g_bqkv);
    cudaGetSymbolAddress((void**)&w1T,   g_w1T);
    cudaGetSymbolAddress((void**)&w2T,   g_w2T);
    cudaGetSymbolAddress((void**)&qkv,   g_qkv);
    cudaGetSymbolAddress((void**)&vT,    g_vT);
    cudaGetSymbolAddress((void**)&at,    g_at);
    cudaGetSymbolAddress((void**)&ao,    g_ao);
    cudaGetSymbolAddress((void**)&x1f,   g_x1f);
    cudaGetSymbolAddress((void**)&x1h,   g_x1h);
    cudaGetSymbolAddress((void**)&hh,    g_hh);
    cudaGetSymbolAddress((void**)&ff,    g_ff);

    const int SMEM = 3 * (2560 + 5120) * 4;   // 92160 B
    cudaFuncSetAttribute((const void*)gemm_h<false, true>,
                         cudaFuncAttributeMaxDynamicSharedMemorySize, SMEM);
    cudaFuncSetAttribute((const void*)gemm_h<false, false>,
                         cudaFuncAttributeMaxDynamicSharedMemorySize, SMEM);
    cudaFuncSetAttribute((const void*)gemm_h<true, true>,
                         cudaFuncAttributeMaxDynamicSharedMemorySize, SMEM);

    dim3 blk(256);
    dim3 tblk(32, 8);

    // --- prep: half input, concat transposed weights, concat bias ---
    f2h_kernel<<<1184, blk>>>((const float4*)x, (__half2*)xh, (long long)MM * DD / 4);
    transpose_f2h<<<dim3(DD/32, DD/32), tblk>>>(Wq, wqkvT,               DD, DD);
    transpose_f2h<<<dim3(DD/32, DD/32), tblk>>>(Wk, wqkvT + DD * DD,     DD, DD);
    transpose_f2h<<<dim3(DD/32, DD/32), tblk>>>(Wv, wqkvT + 2 * DD * DD, DD, DD);
    transpose_f2h<<<dim3(HH/32, DD/32), tblk>>>(W1, w1T, DD, HH);
    transpose_f2h<<<dim3(DD/32, HH/32), tblk>>>(W2, w2T, HH, DD);
    cudaMemcpyAsync(bqkv,          bq, DD * sizeof(float), cudaMemcpyDeviceToDevice);
    cudaMemcpyAsync(bqkv + DD,     bk, DD * sizeof(float), cudaMemcpyDeviceToDevice);
    cudaMemcpyAsync(bqkv + 2 * DD, bv, DD * sizeof(float), cudaMemcpyDeviceToDevice);

    // --- fused QKV projection: [8192, 3072] = xh @ wqkvT^T + bqkv ---
    dim3 gqkv(3 * DD / 256, MM / 128, 1);
    gemm_h<false, true><<<gqkv, blk, SMEM>>>(
        xh, wqkvT, bqkv, qkv, MM, 3 * DD, DD, DD, DD, 0, 0, 0);

    const __half* qh = qkv;                // [8192][1024] view, stride 3072
    const __half* kh = qkv + DD;
    const __half* vh = qkv + 2 * DD;

    // --- logits[b] = k[b] @ q[b]^T (reference quirk), half out into g_at ---
    dim3 gsc(SS / 256, SS / 128, BB);
    gemm_h<false, true><<<gsc, blk, SMEM>>>(
        kh, qh, nullptr, at, SS, SS, DD, 3 * DD, 3 * DD,
        (long long)SS * 3 * DD, (long long)SS * 3 * DD, (long long)SS * SS);

    // --- softmax in-place (scale = 1/32) ---
    softmax_h<<<MM, blk>>>(at, 0.03125f);

    // --- vT[b] = v[b]^T : [1024][4096] half ---
    transpose_h<<<dim3(DD/32, SS/32, BB), tblk>>>(
        vh, vT, SS, DD, 3 * DD, (long long)SS * 3 * DD, (long long)DD * SS);

    // --- ao[b] = attn[b] @ vT[b]^T (fp32 out) ---
    dim3 gav(DD / 256, SS / 128, BB);
    gemm_h<false, false><<<gav, blk, SMEM>>>(
        at, vT, nullptr, ao, SS, DD, SS, SS, SS,
        (long long)SS * SS, (long long)DD * SS, (long long)SS * DD);

    // --- x1 = LayerNorm(x + ao); fp32 + half ---
    add_ln_kernel<<<MM, blk>>>(x, ao, gamma, beta, x1f, x1h);

    // --- h = gelu(x1 @ W1 + b1), half out ---
    dim3 gf1(HH / 256, MM / 128, 1);
    gemm_h<true, true><<<gf1, blk, SMEM>>>(
        x1h, w1T, b1, hh, MM, HH, DD, DD, DD, 0, 0, 0);

    // --- ff = h @ W2 + b2, fp32 out ---
    dim3 gf2(DD / 256, MM / 128, 1);
    gemm_h<false, false><<<gf2, blk, SMEM>>>(
        hh, w2T, b2, ff, MM, DD, HH, HH, HH, 0, 0, 0);

    // --- out = LayerNorm(x1 + ff), fp32 ---
    add_ln_kernel<<<MM, blk>>>(x1f, ff, gamma, beta, out, nullptr);
}

// round 7
// speedup vs baseline: 6.5009x; 1.1301x over previous
#include <cuda_runtime.h>
#include <cuda_fp16.h>
#include <math.h>
#include <stdint.h>

// ---------------------------------------------------------------------------
// B=2, S=4096, D=1024, H=4096, M=B*S=8192
// ---------------------------------------------------------------------------
#define BB   2
#define SS   4096
#define DD   1024
#define HH   4096
#define MM   (BB * SS)

// ---------------------------------------------------------------------------
// Scratch (static device globals; no runtime allocation allowed)
// ---------------------------------------------------------------------------
__device__ __half g_xh   [MM * DD];
__device__ __half g_wqkvT[3 * DD * DD];
__device__ float  g_bqkv [3 * DD];
__device__ __half g_w1T  [(long long)HH * DD];
__device__ __half g_w2T  [(long long)DD * HH];
__device__ __half g_qkv  [(long long)MM * 3 * DD];
__device__ __half g_vT   [(long long)BB * DD * SS];
__device__ __half g_at   [(long long)BB * SS * SS];
__device__ float  g_ao   [MM * DD];
__device__ float  g_x1f  [MM * DD];
__device__ __half g_x1h  [MM * DD];
__device__ __half g_hh   [(long long)MM * HH];
__device__ float  g_ff   [MM * DD];

// ---------------------------------------------------------------------------
// PTX helpers
// ---------------------------------------------------------------------------
__device__ __forceinline__ void mma_f16(float* c, const uint32_t* a, const uint32_t* b) {
    asm volatile(
        "mma.sync.aligned.m16n8k16.row.col.f32.f16.f16.f32 "
        "{%0,%1,%2,%3}, {%4,%5,%6,%7}, {%8,%9}, {%0,%1,%2,%3};\n"
        : "+f"(c[0]), "+f"(c[1]), "+f"(c[2]), "+f"(c[3])
        : "r"(a[0]), "r"(a[1]), "r"(a[2]), "r"(a[3]),
          "r"(b[0]), "r"(b[1]));
}
__device__ __forceinline__ void ldsm_x4(uint32_t* r, uint32_t saddr) {
    asm volatile(
        "ldmatrix.sync.aligned.m8n8.x4.shared.b16 {%0,%1,%2,%3}, [%4];"
        : "=r"(r[0]), "=r"(r[1]), "=r"(r[2]), "=r"(r[3]) : "r"(saddr));
}
__device__ __forceinline__ void cp_async16(uint32_t saddr, const void* gmem) {
    asm volatile("cp.async.cg.shared.global [%0], [%1], 16;\n" :: "r"(saddr), "l"(gmem));
}
__device__ __forceinline__ void cp_commit() {
    asm volatile("cp.async.commit_group;\n");
}
__device__ __forceinline__ void cp_wait1() {
    asm volatile("cp.async.wait_group 1;\n");
}

// ---------------------------------------------------------------------------
// fp16 tensor-core GEMM (NT): C[M,N] = A[M,K] @ Bt[N,K]^T (+bias, +GELU).
// CTA tile 128x256, BK=64, 256 threads = 8 warps of 64x64.
// 3-stage cp.async pipeline, ldmatrix.x4, register frag double-buffering.
// M,N multiples of tile; K multiple of 64 (K/64 >= 2).
// ---------------------------------------------------------------------------
template <bool GELU, bool OUT_HALF>
__global__ void __launch_bounds__(256, 1)
gemm_h(const __half* __restrict__ A, const __half* __restrict__ Bt,
       const float* __restrict__ bias, void* __restrict__ Cv,
       int M, int N, int K, int lda, int ldb,
       long long sA, long long sB, long long sC)
{
    constexpr int BM = 128, BN = 256, BK = 64;
    constexpr int LDH2 = 36;                    // u32 words per smem row (32+4 pad)
    constexpr int A_STAGE = BM * LDH2;          // 4608 words
    constexpr int B_STAGE = BN * LDH2;          // 9216 words
    constexpr int STAGE   = A_STAGE + B_STAGE;  // 13824 words

    extern __shared__ uint32_t smem_u[];
    const uint32_t sbase = (uint32_t)__cvta_generic_to_shared(smem_u);

    A  += (long long)blockIdx.z * sA;
    Bt += (long long)blockIdx.z * sB;

    const int tid  = threadIdx.x;
    const int lane = tid & 31;
    const int wid  = tid >> 5;
    const int m0   = blockIdx.y * BM;
    const int n0   = blockIdx.x * BN;
    const int wm   = (wid & 1) * 64;
    const int wn   = (wid >> 1) * 64;
    const int lr   = lane >> 2;
    const int lc   = lane & 3;

    float acc[4][8][4];
    #pragma unroll
    for (int i = 0; i < 4; ++i)
        #pragma unroll
        for (int j = 0; j < 8; ++j)
            #pragma unroll
            for (int t = 0; t < 4; ++t)
                acc[i][j][t] = 0.0f;

    // ldmatrix per-lane byte offsets within a stage (same mapping as verified)
    uint32_t a_off[4], b_off[4];
    {
        int arow  = wm + (lane & 15);
        int acol2 = (lane >> 4) * 4;
        #pragma unroll
        for (int mi = 0; mi < 4; ++mi)
            a_off[mi] = (uint32_t)(((arow + mi * 16) * LDH2 + acol2) * 4);
        int brow  = wn + (lane & 7) + ((lane >> 4) & 1) * 8;
        int bcol2 = ((lane >> 3) & 1) * 4;
        #pragma unroll
        for (int p = 0; p < 4; ++p)
            b_off[p] = (uint32_t)((A_STAGE + (brow + p * 16) * LDH2 + bcol2) * 4);
    }

    auto load_tile = [&](int t) {
        const uint32_t stg = sbase + (uint32_t)((t % 3) * STAGE * 4);
        const int k0 = t * BK;
        // A: 128 rows x 8 chunks of 16B; 4 per thread
        #pragma unroll
        for (int p = 0; p < 4; ++p) {
            int idx = tid + p * 256;
            int row = idx >> 3, ch = idx & 7;
            cp_async16(stg + (uint32_t)((row * LDH2 + ch * 4) * 4),
                       A + (long long)(m0 + row) * lda + k0 + ch * 8);
        }
        // B: 256 rows x 8 chunks; 8 per thread
        #pragma unroll
        for (int p = 0; p < 8; ++p) {
            int idx = tid + p * 256;
            int row = idx >> 3, ch = idx & 7;
            cp_async16(stg + (uint32_t)((A_STAGE + row * LDH2 + ch * 4) * 4),
                       Bt + (long long)(n0 + row) * ldb + k0 + ch * 8);
        }
    };

    uint32_t af[2][4][4], bf[2][8][2];
    auto load_frags = [&](uint32_t stg, int ks, int buf) {
        const uint32_t kb = (uint32_t)(ks * 32);      // 8 u32 per k16 step
        #pragma unroll
        for (int mi = 0; mi < 4; ++mi)
            ldsm_x4(af[buf][mi], stg + a_off[mi] + kb);
        #pragma unroll
        for (int p = 0; p < 4; ++p) {
            uint32_t r[4];
            ldsm_x4(r, stg + b_off[p] + kb);
            bf[buf][2 * p + 0][0] = r[0];
            bf[buf][2 * p + 0][1] = r[1];
            bf[buf][2 * p + 1][0] = r[2];
            bf[buf][2 * p + 1][1] = r[3];
        }
    };

    const int NIT = K / BK;
    load_tile(0); cp_commit();
    load_tile(1); cp_commit();

    for (int it = 0; it < NIT; ++it) {
        cp_wait1();                 // stage `it` resident
        __syncthreads();            // all warps done reading stage (it+2)%3
        if (it + 2 < NIT) load_tile(it + 2);
        cp_commit();                // exactly one group per iteration

        const uint32_t stg = sbase + (uint32_t)((it % 3) * STAGE * 4);
        load_frags(stg, 0, 0);
        #pragma unroll
        for (int ks = 0; ks < 4; ++ks) {
            const int cur = ks & 1;
            if (ks < 3) load_frags(stg, ks + 1, cur ^ 1);
            #pragma unroll
            for (int mi = 0; mi < 4; ++mi)
                #pragma unroll
                for (int nj = 0; nj < 8; ++nj)
                    mma_f16(acc[mi][nj], af[cur][mi], bf[cur][nj]);
        }
    }

    // ---- epilogue ----
    float*  Cf = (float*) Cv + (long long)blockIdx.z * sC;
    __half* Ch = (__half*)Cv + (long long)blockIdx.z * sC;
    #pragma unroll
    for (int mi = 0; mi < 4; ++mi) {
        #pragma unroll
        for (int nj = 0; nj < 8; ++nj) {
            const int col = n0 + wn + nj * 8 + lc * 2;
            float b0 = 0.0f, b1 = 0.0f;
            if (bias) { b0 = bias[col]; b1 = bias[col + 1]; }
            #pragma unroll
            for (int hf = 0; hf < 2; ++hf) {
                const int row = m0 + wm + mi * 16 + lr + hf * 8;
                float v0 = acc[mi][nj][hf * 2 + 0] + b0;
                float v1 = acc[mi][nj][hf * 2 + 1] + b1;
                if (GELU) {
                    v0 = 0.5f * v0 * (1.0f + erff(v0 * 0.70710678118654752f));
                    v1 = 0.5f * v1 * (1.0f + erff(v1 * 0.70710678118654752f));
                }
                if (OUT_HALF) {
                    *(__half2*)(Ch + (long long)row * N + col) = __floats2half2_rn(v0, v1);
                } else {
                    *(float2*)(Cf + (long long)row * N + col) = make_float2(v0, v1);
                }
            }
        }
    }
}

// ---------------------------------------------------------------------------
// Elementwise fp32 -> half
// ---------------------------------------------------------------------------
__global__ void __launch_bounds__(256)
f2h_kernel(const float4* __restrict__ in, __half2* __restrict__ out, long long n4)
{
    long long i = (long long)blockIdx.x * blockDim.x + threadIdx.x;
    long long stride = (long long)gridDim.x * blockDim.x;
    for (; i < n4; i += stride) {
        float4 v = in[i];
        out[2 * i + 0] = __floats2half2_rn(v.x, v.y);
        out[2 * i + 1] = __floats2half2_rn(v.z, v.w);
    }
}

// ---------------------------------------------------------------------------
// Transpose fp32 [R][C] -> half [C][R]
// ---------------------------------------------------------------------------
__global__ void __launch_bounds__(256)
transpose_f2h(const float* __restrict__ in, __half* __restrict__ out, int R, int C)
{
    __shared__ float t[32][33];
    int x = blockIdx.x * 32 + threadIdx.x;
    int y = blockIdx.y * 32 + threadIdx.y;
    #pragma unroll
    for (int i = 0; i < 32; i += 8)
        t[threadIdx.y + i][threadIdx.x] = in[(long long)(y + i) * C + x];
    __syncthreads();
    x = blockIdx.y * 32 + threadIdx.x;
    y = blockIdx.x * 32 + threadIdx.y;
    #pragma unroll
    for (int i = 0; i < 32; i += 8)
        out[(long long)(y + i) * R + x] = __float2half_rn(t[threadIdx.x][threadIdx.y + i]);
}

// ---------------------------------------------------------------------------
// Transpose half [R][C-view] -> half [C][R], input row stride ldIn, batched
// ---------------------------------------------------------------------------
__global__ void __launch_bounds__(256)
transpose_h(const __half* __restrict__ in, __half* __restrict__ out,
            int R, int C, int ldIn, long long sIn, long long sOut)
{
    __shared__ __half t[32][40];
    in  += (long long)blockIdx.z * sIn;
    out += (long long)blockIdx.z * sOut;
    int x = blockIdx.x * 32 + threadIdx.x;
    int y = blockIdx.y * 32 + threadIdx.y;
    #pragma unroll
    for (int i = 0; i < 32; i += 8)
        t[threadIdx.y + i][threadIdx.x] = in[(long long)(y + i) * ldIn + x];
    __syncthreads();
    x = blockIdx.y * 32 + threadIdx.x;
    y = blockIdx.x * 32 + threadIdx.y;
    #pragma unroll
    for (int i = 0; i < 32; i += 8)
        out[(long long)(y + i) * R + x] = t[threadIdx.x][threadIdx.y + i];
}

// ---------------------------------------------------------------------------
// Block reduction helper (sum or max), 256 threads
// ---------------------------------------------------------------------------
__device__ __forceinline__ float block_reduce(float v, bool do_max) {
    __shared__ float sh[33];
    #pragma unroll
    for (int o = 16; o > 0; o >>= 1) {
        float t = __shfl_xor_sync(0xffffffffu, v, o);
        v = do_max ? fmaxf(v, t) : (v + t);
    }
    const int lane = threadIdx.x & 31;
    const int wid  = threadIdx.x >> 5;
    if (lane == 0) sh[wid] = v;
    __syncthreads();
    if (wid == 0) {
        int nw = blockDim.x >> 5;
        v = (lane < nw) ? sh[lane] : (do_max ? -INFINITY : 0.0f);
        #pragma unroll
        for (int o = 16; o > 0; o >>= 1) {
            float t = __shfl_xor_sync(0xffffffffu, v, o);
            v = do_max ? fmaxf(v, t) : (v + t);
        }
        if (lane == 0) sh[32] = v;
    }
    __syncthreads();
    float r = sh[32];
    __syncthreads();
    return r;
}

// ---------------------------------------------------------------------------
// Softmax in-place on half rows of 4096 (logits -> probs)
// ---------------------------------------------------------------------------
__global__ void __launch_bounds__(256)
softmax_h(__half* __restrict__ at, float scale)
{
    constexpr int T2 = SS / 2, NT = 256, VPT = T2 / NT;
    __half2* row = (__half2*)(at + (long long)blockIdx.x * SS);
    const int tid = threadIdx.x;

    float2 r[VPT];
    float mx = -INFINITY;
    #pragma unroll
    for (int i = 0; i < VPT; ++i) {
        float2 f = __half22float2(row[tid + i * NT]);
        r[i].x = f.x * scale; r[i].y = f.y * scale;
        mx = fmaxf(mx, fmaxf(r[i].x, r[i].y));
    }
    mx = block_reduce(mx, true);

    float s = 0.0f;
    #pragma unroll
    for (int i = 0; i < VPT; ++i) {
        r[i].x = expf(r[i].x - mx);
        r[i].y = expf(r[i].y - mx);
        s += r[i].x + r[i].y;
    }
    s = block_reduce(s, false);
    float inv = 1.0f / s;

    #pragma unroll
    for (int i = 0; i < VPT; ++i)
        row[tid + i * NT] = __floats2half2_rn(r[i].x * inv, r[i].y * inv);
}

// ---------------------------------------------------------------------------
// out = LayerNorm(X + R) * gamma + beta; fp32 out, optional half copy
// ---------------------------------------------------------------------------
__global__ void __launch_bounds__(256)
add_ln_kernel(const float* __restrict__ X, const float* __restrict__ R,
              const float* __restrict__ gamma, const float* __restrict__ beta,
              float* __restrict__ O, __half* __restrict__ Oh)
{
    constexpr int D = DD;
    const long long base = (long long)blockIdx.x * D;
    const int d = threadIdx.x * 4;

    float4 xv = *(const float4*)(X + base + d);
    float4 rv = *(const float4*)(R + base + d);
    float4 v  = make_float4(xv.x + rv.x, xv.y + rv.y, xv.z + rv.z, xv.w + rv.w);

    float mean = block_reduce(v.x + v.y + v.z + v.w, false) * (1.0f / D);

    float4 dv = make_float4(v.x - mean, v.y - mean, v.z - mean, v.w - mean);
    float var = block_reduce(dv.x * dv.x + dv.y * dv.y + dv.z * dv.z + dv.w * dv.w,
                             false) * (1.0f / D);
    float inv = rsqrtf(var + 1e-5f);

    float4 gv = *(const float4*)(gamma + d);
    float4 bv = *(const float4*)(beta + d);
    float4 o;
    o.x = dv.x * inv * gv.x + bv.x;
    o.y = dv.y * inv * gv.y + bv.y;
    o.z = dv.z * inv * gv.z + bv.z;
    o.w = dv.w * inv * gv.w + bv.w;
    *(float4*)(O + base + d) = o;
    if (Oh) {
        *(__half2*)(Oh + base + d)     = __floats2half2_rn(o.x, o.y);
        *(__half2*)(Oh + base + d + 2) = __floats2half2_rn(o.z, o.w);
    }
}

// ---------------------------------------------------------------------------
// kernel_launch
// Inputs: input_embedding, Wq, bq, Wk, bk, Wv, bv, W1, b1, W2, b2, gamma, beta
// ---------------------------------------------------------------------------
extern "C" void kernel_launch(void* const* d_in, const int* /*in_sizes*/, int /*n_in*/,
                              void* d_out, int /*out_size*/)
{
    const float* x     = (const float*)d_in[0];
    const float* Wq    = (const float*)d_in[1];
    const float* bq    = (const float*)d_in[2];
    const float* Wk    = (const float*)d_in[3];
    const float* bk    = (const float*)d_in[4];
    const float* Wv    = (const float*)d_in[5];
    const float* bv    = (const float*)d_in[6];
    const float* W1    = (const float*)d_in[7];
    const float* b1    = (const float*)d_in[8];
    const float* W2    = (const float*)d_in[9];
    const float* b2    = (const float*)d_in[10];
    const float* gamma = (const float*)d_in[11];
    const float* beta  = (const float*)d_in[12];
    float* out = (float*)d_out;

    __half *xh, *wqkvT, *w1T, *w2T, *qkv, *vT, *at, *x1h, *hh;
    float *bqkv, *ao, *x1f, *ff;
    cudaGetSymbolAddress((void**)&xh,    g_xh);
    cudaGetSymbolAddress((void**)&wqkvT, g_wqkvT);
    cudaGetSymbolAddress((void**)&bqkv,  g_bqkv);
    cudaGetSymbolAddress((void**)&w1T,   g_w1T);
    cudaGetSymbolAddress((void**)&w2T,   g_w2T);
    cudaGetSymbolAddress((void**)&qkv,   g_qkv);
    cudaGetSymbolAddress((void**)&vT,    g_vT);
    cudaGetSymbolAddress((void**)&at,    g_at);
    cudaGetSymbolAddress((void**)&ao,    g_ao);
    cudaGetSymbolAddress((void**)&x1f,   g_x1f);
    cudaGetSymbolAddress((void**)&x1h,   g_x1h);
    cudaGetSymbolAddress((void**)&hh,    g_hh);
    cudaGetSymbolAddress((void**)&ff,    g_ff);

    const int SMEM = 3 * 13824 * 4;   // 165888 B
    cudaFuncSetAttribute((const void*)gemm_h<false, true>,
                         cudaFuncAttributeMaxDynamicSharedMemorySize, SMEM);
    cudaFuncSetAttribute((const void*)gemm_h<false, false>,
                         cudaFuncAttributeMaxDynamicSharedMemorySize, SMEM);
    cudaFuncSetAttribute((const void*)gemm_h<true, true>,
                         cudaFuncAttributeMaxDynamicSharedMemorySize, SMEM);

    dim3 blk(256);
    dim3 tblk(32, 8);

    // --- prep: half input, concat transposed weights, concat bias ---
    f2h_kernel<<<1184, blk>>>((const float4*)x, (__half2*)xh, (long long)MM * DD / 4);
    transpose_f2h<<<dim3(DD/32, DD/32), tblk>>>(Wq, wqkvT,               DD, DD);
    transpose_f2h<<<dim3(DD/32, DD/32), tblk>>>(Wk, wqkvT + DD * DD,     DD, DD);
    transpose_f2h<<<dim3(DD/32, DD/32), tblk>>>(Wv, wqkvT + 2 * DD * DD, DD, DD);
    transpose_f2h<<<dim3(HH/32, DD/32), tblk>>>(W1, w1T, DD, HH);
    transpose_f2h<<<dim3(DD/32, HH/32), tblk>>>(W2, w2T, HH, DD);
    cudaMemcpyAsync(bqkv,          bq, DD * sizeof(float), cudaMemcpyDeviceToDevice);
    cudaMemcpyAsync(bqkv + DD,     bk, DD * sizeof(float), cudaMemcpyDeviceToDevice);
    cudaMemcpyAsync(bqkv + 2 * DD, bv, DD * sizeof(float), cudaMemcpyDeviceToDevice);

    // --- fused QKV projection: [8192, 3072] ---
    dim3 gqkv(3 * DD / 256, MM / 128, 1);
    gemm_h<false, true><<<gqkv, blk, SMEM>>>(
        xh, wqkvT, bqkv, qkv, MM, 3 * DD, DD, DD, DD, 0, 0, 0);

    const __half* qh = qkv;
    const __half* kh = qkv + DD;
    const __half* vh = qkv + 2 * DD;

    // --- logits[b] = k[b] @ q[b]^T (reference quirk), half out ---
    dim3 gsc(SS / 256, SS / 128, BB);
    gemm_h<false, true><<<gsc, blk, SMEM>>>(
        kh, qh, nullptr, at, SS, SS, DD, 3 * DD, 3 * DD,
        (long long)SS * 3 * DD, (long long)SS * 3 * DD, (long long)SS * SS);

    // --- softmax in-place (scale = 1/32) ---
    softmax_h<<<MM, blk>>>(at, 0.03125f);

    // --- vT[b] = v[b]^T ---
    transpose_h<<<dim3(DD/32, SS/32, BB), tblk>>>(
        vh, vT, SS, DD, 3 * DD, (long long)SS * 3 * DD, (long long)DD * SS);

    // --- ao[b] = attn[b] @ vT[b]^T (fp32 out) ---
    dim3 gav(DD / 256, SS / 128, BB);
    gemm_h<false, false><<<gav, blk, SMEM>>>(
        at, vT, nullptr, ao, SS, DD, SS, SS, SS,
        (long long)SS * SS, (long long)DD * SS, (long long)SS * DD);

    // --- x1 = LayerNorm(x + ao); fp32 + half ---
    add_ln_kernel<<<MM, blk>>>(x, ao, gamma, beta, x1f, x1h);

    // --- h = gelu(x1 @ W1 + b1), half out ---
    dim3 gf1(HH / 256, MM / 128, 1);
    gemm_h<true, true><<<gf1, blk, SMEM>>>(
        x1h, w1T, b1, hh, MM, HH, DD, DD, DD, 0, 0, 0);

    // --- ff = h @ W2 + b2, fp32 out ---
    dim3 gf2(DD / 256, MM / 128, 1);
    gemm_h<false, false><<<gf2, blk, SMEM>>>(
        hh, w2T, b2, ff, MM, DD, HH, HH, HH, 0, 0, 0);

    // --- out = LayerNorm(x1 + ff), fp32 ---
    add_ln_kernel<<<MM, blk>>>(x1f, ff, gamma, beta, out, nullptr);
}